// round 15
// baseline (speedup 1.0000x reference)
#include <cuda_runtime.h>
#include <cuda_fp16.h>
#include <cstdint>
#include <cstddef>

#define BB 4
#define T0C 256
#define T1C 768
#define TC 1024
#define DC 2048
#define NQ 8
#define HC 256
#define FC 16384
#define NHD 2048
#define QKVW 2560
#define MROWS 8192
#define NEGC (-2.3819763e+38f)

// ---------------- fp16 weights ----------------
__device__ __align__(16) __half g_qwh[(size_t)2*NHD*DC];
__device__ __align__(16) __half g_kwh[(size_t)2*HC*DC];
__device__ __align__(16) __half g_vwh[(size_t)2*HC*DC];
__device__ __align__(16) __half g_owh[(size_t)2*DC*NHD];
__device__ __align__(16) __half g_gwh[(size_t)2*FC*DC];
__device__ __align__(16) __half g_uwh[(size_t)2*FC*DC];
__device__ __align__(16) __half g_dwh[(size_t)2*DC*FC];

// ---------------- activations ----------------
__device__ __align__(16) __half g_preh[(size_t)BB*TC*DC];
__device__ float g_qkvf [(size_t)BB*TC*QKVW];
__device__ __align__(16) __half g_qhh [(size_t)BB*TC*NHD];
__device__ __align__(16) __half g_kdhh[(size_t)BB*TC*HC];
__device__ __align__(16) __half g_vTh [(size_t)BB*HC*TC];
__device__ float g_S    [(size_t)BB*MROWS*TC];
__device__ __align__(16) __half g_Ph  [(size_t)BB*MROWS*TC];
__device__ __align__(16) __half g_ench[(size_t)BB*TC*NHD];
__device__ float g_resid[(size_t)BB*TC*DC];
__device__ __align__(16) __half g_hidh[(size_t)BB*TC*DC];
__device__ __align__(16) __half g_guh [(size_t)BB*TC*FC];

__device__ __forceinline__ uint32_t smem_u32(const void* p) {
    uint32_t a;
    asm("{ .reg .u64 t; cvta.to.shared.u64 t, %1; cvt.u32.u64 %0, t; }" : "=r"(a) : "l"(p));
    return a;
}
__device__ __forceinline__ void cp16(uint32_t dst, const void* src) {
    asm volatile("cp.async.ca.shared.global [%0], [%1], 16;" :: "r"(dst), "l"(src));
}
#define CP_COMMIT() asm volatile("cp.async.commit_group;" ::: "memory")
#define CP_WAIT(n)  asm volatile("cp.async.wait_group %0;" :: "n"(n) : "memory")

__device__ __forceinline__ void ldsm4(uint32_t* r, uint32_t addr) {
    asm volatile("ldmatrix.sync.aligned.m8n8.x4.shared.b16 {%0,%1,%2,%3}, [%4];"
        : "=r"(r[0]), "=r"(r[1]), "=r"(r[2]), "=r"(r[3]) : "r"(addr));
}
__device__ __forceinline__ void mma16(float* d, const uint32_t* a, const uint32_t* b) {
    asm volatile(
        "mma.sync.aligned.m16n8k16.row.col.f32.f16.f16.f32 "
        "{%0,%1,%2,%3}, {%4,%5,%6,%7}, {%8,%9}, {%0,%1,%2,%3};"
        : "+f"(d[0]), "+f"(d[1]), "+f"(d[2]), "+f"(d[3])
        : "r"(a[0]), "r"(a[1]), "r"(a[2]), "r"(a[3]), "r"(b[0]), "r"(b[1]));
}
__device__ __forceinline__ float gelu_tanh(float x) {
    float x3 = x * x * x;
    return 0.5f * x * (1.f + tanhf(0.7978845608028654f * (x + 0.044715f * x3)));
}
__device__ __forceinline__ uint32_t h2u(__half2 h) { return *(uint32_t*)&h; }

// ================= fp16 cp.async multistage GEMM (8 warps, 64x32 warp tile) =================
// CTA 128x128, 8 warps (2 m x 4 n), K-chunk 64, 3 stages, 1 barrier/chunk,
// tail-sound commits. 16 warps/SM at 2 CTAs/SM for HMMA latency hiding.
// MODE 1: fp32 acc + X(seg) -> resid    MODE 2: fp32 acc + Radd -> scattered d_out
// MODE 6: fused QKV -> fp32 (y: 0-15 qw, 16-17 kw, 18-19 vw)
// MODE 7: fp32 scores (z=batch); fully-masked tiles skipped (no writes)
// MODE 8: fp16 enc (z=batch); K-loop truncated to valid span (tail P is zero)
#define SROWH 72
#define NSTAGE 3
#define STGH (2 * 128 * SROWH)

template <int MODE>
__global__ void __launch_bounds__(256, 2)
mma_gemm(const __half* __restrict__ A,
         const __half* __restrict__ W0, const __half* __restrict__ W1,
         const __half* __restrict__ K0, const __half* __restrict__ K1,
         const __half* __restrict__ V0, const __half* __restrict__ V1,
         void* __restrict__ Cv, int Nout, int Kdim,
         const float* __restrict__ X0, const float* __restrict__ X1,
         const float* __restrict__ Radd) {
    extern __shared__ __half smh[];
    uint32_t sbase = smem_u32(smh);
    int tid = threadIdx.x, wid = tid >> 5, lane = tid & 31;
    int warp_m = wid & 1, warp_n = wid >> 1;      // 2 x 4 warps, 64x32 tiles
    int rm0 = blockIdx.x * 128;
    int rn0 = blockIdx.y * 128;
    int z = blockIdx.z;

    if (MODE == 7) {
        int tt_max = (rm0 >> 3) + 15;
        if (rn0 >= T0C && rn0 > tt_max) return;   // fully masked tile
    }

    const __half* Wa; const __half* Wb; int wr0 = rn0;
    if (MODE == 6) {
        if (blockIdx.y < 16)      { Wa = W0; Wb = W1; wr0 = blockIdx.y * 128; }
        else if (blockIdx.y < 18) { Wa = K0; Wb = K1; wr0 = (blockIdx.y - 16) * 128; }
        else                      { Wa = V0; Wb = V1; wr0 = (blockIdx.y - 18) * 128; }
    } else { Wa = W0; Wb = W1; }

    const __half* W;
    float* Cf = (float*)Cv;
    __half* Ch = (__half*)Cv;
    if (MODE == 7) {
        A += (size_t)z * MROWS * HC;
        W = W0 + (size_t)z * TC * HC;
        Cf += (size_t)z * MROWS * TC;
    } else if (MODE == 8) {
        A += (size_t)z * MROWS * TC;
        W = W0 + (size_t)z * HC * TC;
        Ch += (size_t)z * MROWS * HC;
    } else {
        W = ((rm0 & 1023) < T0C) ? Wa : Wb;
    }

    const uint32_t a_off =
        (uint32_t)(((warp_m * 64 + (lane & 15)) * SROWH + (lane >> 4) * 8) * 2);
    const uint32_t b_off =
        (uint32_t)((128 * SROWH +
                    (warp_n * 32 + (lane & 7) + ((lane >> 4) & 1) * 8) * SROWH +
                    ((lane >> 3) & 1) * 8) * 2);

    float acc[4][4][4];
    #pragma unroll
    for (int t = 0; t < 4; t++)
        #pragma unroll
        for (int j = 0; j < 4; j++)
            #pragma unroll
            for (int e = 0; e < 4; e++) acc[t][j][e] = 0.f;

    auto issue = [&](int c) {
        int stg = c - (c / NSTAGE) * NSTAGE;
        uint32_t sb = sbase + stg * (STGH * 2);
        int kb = c << 6;
        #pragma unroll
        for (int it = 0; it < 8; it++) {
            int idx = it * 256 + tid;
            int row = (idx >> 3) & 127;
            int sg = (idx & 7) << 3;
            if (idx < 1024)
                cp16(sb + (uint32_t)(row * SROWH + sg) * 2,
                     A + (size_t)(rm0 + row) * Kdim + kb + sg);
            else
                cp16(sb + (uint32_t)(128 * SROWH + row * SROWH + sg) * 2,
                     W + (size_t)(wr0 + row) * Kdim + kb + sg);
        }
    };

    auto compute = [&](int stg) {
        uint32_t sb = sbase + stg * (STGH * 2);
        #pragma unroll
        for (int ks = 0; ks < 4; ks++) {
            uint32_t af[4][4], bf[4][2];
            #pragma unroll
            for (int t = 0; t < 4; t++)
                ldsm4(af[t], sb + a_off + (uint32_t)((t * 16 * SROWH + ks * 16) * 2));
            #pragma unroll
            for (int p = 0; p < 2; p++)
                ldsm4(&bf[2 * p][0], sb + b_off + (uint32_t)((p * 16 * SROWH + ks * 16) * 2));
            #pragma unroll
            for (int t = 0; t < 4; t++)
                #pragma unroll
                for (int j = 0; j < 4; j++)
                    mma16(acc[t][j], af[t], bf[j]);
        }
    };

    int nch;
    if (MODE == 8) {
        int kmax = max(T0C, (rm0 >> 3) + 16);
        nch = (kmax + 63) >> 6;
    } else {
        nch = Kdim >> 6;
    }

    issue(0); CP_COMMIT();
    issue(1); CP_COMMIT();
    int stg = 0;
    for (int c = 0; c < nch; c++) {
        CP_WAIT(1);
        __syncthreads();
        compute(stg);
        if (++stg == NSTAGE) stg = 0;
        int nx = c + NSTAGE - 1;
        if (nx < nch) issue(nx);
        CP_COMMIT();
    }

    // ---------------- epilogue ----------------
    #pragma unroll
    for (int t = 0; t < 4; t++) {
        #pragma unroll
        for (int j = 0; j < 4; j++) {
            int c = rn0 + warp_n * 32 + j * 8 + (lane & 3) * 2;
            #pragma unroll
            for (int h = 0; h < 2; h++) {
                int r = rm0 + warp_m * 64 + t * 16 + (lane >> 2) + h * 8;
                float v0 = acc[t][j][h * 2 + 0];
                float v1 = acc[t][j][h * 2 + 1];
                if (MODE == 6) {
                    float2 v = {v0, v1};
                    *(float2*)&Cf[(size_t)r * Nout + c] = v;
                } else if (MODE == 8) {
                    *(__half2*)&Ch[(size_t)r * Nout + c] = __floats2half2_rn(v0, v1);
                } else if (MODE == 1) {
                    int b = r >> 10, tt = r & 1023;
                    const float* xp = (tt < T0C)
                        ? X0 + ((size_t)b * T0C + tt) * DC + c
                        : X1 + ((size_t)b * T1C + (tt - T0C)) * DC + c;
                    float2 xv = *(const float2*)xp;
                    float2 v = {v0 + xv.x, v1 + xv.y};
                    *(float2*)&Cf[(size_t)r * DC + c] = v;
                } else if (MODE == 2) {
                    float2 rv = *(const float2*)&Radd[(size_t)r * DC + c];
                    int b = r >> 10, tt = r & 1023;
                    size_t dst = (tt < T0C)
                        ? ((size_t)b * T0C + tt) * DC + c
                        : (size_t)BB * T0C * DC + ((size_t)b * T1C + (tt - T0C)) * DC + c;
                    float2 v = {v0 + rv.x, v1 + rv.y};
                    *(float2*)&Cf[dst] = v;
                } else if (MODE == 7) {
                    float2 v = {v0, v1};
                    *(float2*)&Cf[(size_t)r * TC + c] = v;
                }
            }
        }
    }
}

// ================= fused gate+up FFN kernel (ldmatrix, 1 barrier/chunk) =================
#define STGG (384 * SROWH)

__global__ void __launch_bounds__(256, 1)
ffn_gateup(const __half* __restrict__ A,
           const __half* __restrict__ G0, const __half* __restrict__ G1,
           const __half* __restrict__ U0, const __half* __restrict__ U1,
           __half* __restrict__ Cg) {
    extern __shared__ __half smh[];
    uint32_t sbase = smem_u32(smh);
    int tid = threadIdx.x, wid = tid >> 5, lane = tid & 31;
    int w4 = wid & 3;
    int is_up = wid >> 2;
    int warp_m = w4 & 1, warp_n = w4 >> 1;
    int rm0 = blockIdx.x * 128;
    int rn0 = blockIdx.y * 128;
    bool seg1 = (rm0 & 1023) >= T0C;
    const __half* Wg = seg1 ? G1 : G0;
    const __half* Wu = seg1 ? U1 : U0;

    const uint32_t a_off =
        (uint32_t)(((warp_m * 64 + (lane & 15)) * SROWH + (lane >> 4) * 8) * 2);
    const uint32_t b_off =
        (uint32_t)(((128 + is_up * 128) * SROWH +
                    (warp_n * 64 + (lane & 7) + ((lane >> 4) & 1) * 8) * SROWH +
                    ((lane >> 3) & 1) * 8) * 2);

    float acc[4][8][4];
    #pragma unroll
    for (int t = 0; t < 4; t++)
        #pragma unroll
        for (int j = 0; j < 8; j++)
            #pragma unroll
            for (int e = 0; e < 4; e++) acc[t][j][e] = 0.f;

    auto issue = [&](int c) {
        int stg = c - (c / NSTAGE) * NSTAGE;
        uint32_t sb = sbase + stg * (STGG * 2);
        int kb = c << 6;
        #pragma unroll
        for (int it = 0; it < 12; it++) {
            int idx = it * 256 + tid;
            int row = idx >> 3;
            int sg = (idx & 7) << 3;
            const __half* src;
            if (row < 128)
                src = A + (size_t)(rm0 + row) * DC + kb + sg;
            else if (row < 256)
                src = Wg + (size_t)(rn0 + row - 128) * DC + kb + sg;
            else
                src = Wu + (size_t)(rn0 + row - 256) * DC + kb + sg;
            cp16(sb + (uint32_t)(row * SROWH + sg) * 2, src);
        }
    };

    auto compute = [&](int stg) {
        uint32_t sb = sbase + stg * (STGG * 2);
        #pragma unroll
        for (int ks = 0; ks < 4; ks++) {
            uint32_t af[4][4], bf[8][2];
            #pragma unroll
            for (int t = 0; t < 4; t++)
                ldsm4(af[t], sb + a_off + (uint32_t)((t * 16 * SROWH + ks * 16) * 2));
            #pragma unroll
            for (int p = 0; p < 4; p++)
                ldsm4(&bf[2 * p][0], sb + b_off + (uint32_t)((p * 16 * SROWH + ks * 16) * 2));
            #pragma unroll
            for (int t = 0; t < 4; t++)
                #pragma unroll
                for (int j = 0; j < 8; j++)
                    mma16(acc[t][j], af[t], bf[j]);
        }
    };

    const int nch = DC >> 6;
    issue(0); CP_COMMIT();
    issue(1); CP_COMMIT();
    int stg = 0;
    for (int c = 0; c < nch; c++) {
        CP_WAIT(1);
        __syncthreads();
        compute(stg);
        if (++stg == NSTAGE) stg = 0;
        int nx = c + NSTAGE - 1;
        if (nx < nch) issue(nx);
        CP_COMMIT();
    }

    CP_WAIT(0);
    __syncthreads();

    float* gt = (float*)smh;
    if (!is_up) {
        #pragma unroll
        for (int t = 0; t < 4; t++)
            #pragma unroll
            for (int j = 0; j < 8; j++) {
                int cl = warp_n * 64 + j * 8 + (lane & 3) * 2;
                #pragma unroll
                for (int h = 0; h < 2; h++) {
                    int rl = warp_m * 64 + t * 16 + (lane >> 2) + h * 8;
                    gt[rl * 132 + cl]     = gelu_tanh(acc[t][j][h * 2 + 0]);
                    gt[rl * 132 + cl + 1] = gelu_tanh(acc[t][j][h * 2 + 1]);
                }
            }
    }
    __syncthreads();
    if (is_up) {
        #pragma unroll
        for (int t = 0; t < 4; t++)
            #pragma unroll
            for (int j = 0; j < 8; j++) {
                int cl = warp_n * 64 + j * 8 + (lane & 3) * 2;
                int c = rn0 + cl;
                #pragma unroll
                for (int h = 0; h < 2; h++) {
                    int rl = warp_m * 64 + t * 16 + (lane >> 2) + h * 8;
                    int r = rm0 + rl;
                    float g0 = gt[rl * 132 + cl];
                    float g1 = gt[rl * 132 + cl + 1];
                    *(__half2*)&Cg[(size_t)r * FC + c] =
                        __floats2half2_rn(g0 * acc[t][j][h * 2 + 0],
                                          g1 * acc[t][j][h * 2 + 1]);
                }
            }
    }
}

// ================= split weight conversion =================
template <int NR>
struct CvtArgsN {
    const float4* s[NR];
    uint2* d[NR];
    size_t sz[NR];
};

template <int NR>
__global__ void cvt_n(CvtArgsN<NR> a) {
    size_t i = (size_t)blockIdx.x * 256 + threadIdx.x;
    size_t base = 0;
    #pragma unroll
    for (int r = 0; r < NR; r++) {
        if (i < base + a.sz[r]) {
            size_t k = i - base;
            float4 v = a.s[r][k];
            __half2 h0 = __floats2half2_rn(v.x, v.y);
            __half2 h1 = __floats2half2_rn(v.z, v.w);
            uint2 u = {h2u(h0), h2u(h1)};
            a.d[r][k] = u;
            return;
        }
        base += a.sz[r];
    }
}

#define Q4 ((size_t)NHD * DC / 4)
#define KV4 ((size_t)HC * DC / 4)
#define G4 ((size_t)FC * DC / 4)

// ================= elementwise =================
__device__ __forceinline__ float warp_sum(float v) {
    #pragma unroll
    for (int o = 16; o; o >>= 1) v += __shfl_down_sync(0xffffffffu, v, o);
    return v;
}

__global__ void rms_seg_kernel(const float* __restrict__ x0, const float* __restrict__ x1,
                               const float* __restrict__ s0, const float* __restrict__ s1,
                               __half* __restrict__ out) {
    int row = blockIdx.x;
    int b = row >> 10, t = row & 1023;
    const float* x; const float* s;
    if (t < T0C) { x = x0 + ((size_t)b*T0C + t)*DC; s = s0; }
    else         { x = x1 + ((size_t)b*T1C + (t - T0C))*DC; s = s1; }
    float ss = 0.f;
    for (int d = threadIdx.x; d < DC; d += 256) { float v = x[d]; ss += v*v; }
    __shared__ float red[8];
    ss = warp_sum(ss);
    if ((threadIdx.x & 31) == 0) red[threadIdx.x >> 5] = ss;
    __syncthreads();
    if (threadIdx.x < 8) {
        float v = red[threadIdx.x];
        #pragma unroll
        for (int o = 4; o; o >>= 1) v += __shfl_down_sync(0xffu, v, o);
        if (threadIdx.x == 0) red[0] = v;
    }
    __syncthreads();
    float inv = rsqrtf(red[0] * (1.f / DC) + 1e-6f);
    __half* o = out + (size_t)row * DC;
    for (int d = threadIdx.x; d < DC; d += 256)
        o[d] = __float2half(x[d] * inv * (1.f + s[d]));
}

__global__ void rms_cont_kernel(const float* __restrict__ xin,
                                const float* __restrict__ s0, const float* __restrict__ s1,
                                __half* __restrict__ out) {
    int row = blockIdx.x;
    int t = row & 1023;
    const float* x = xin + (size_t)row * DC;
    const float* s = (t < T0C) ? s0 : s1;
    float ss = 0.f;
    for (int d = threadIdx.x; d < DC; d += 256) { float v = x[d]; ss += v*v; }
    __shared__ float red[8];
    ss = warp_sum(ss);
    if ((threadIdx.x & 31) == 0) red[threadIdx.x >> 5] = ss;
    __syncthreads();
    if (threadIdx.x < 8) {
        float v = red[threadIdx.x];
        #pragma unroll
        for (int o = 4; o; o >>= 1) v += __shfl_down_sync(0xffu, v, o);
        if (threadIdx.x == 0) red[0] = v;
    }
    __syncthreads();
    float inv = rsqrtf(red[0] * (1.f / DC) + 1e-6f);
    __half* o = out + (size_t)row * DC;
    for (int d = threadIdx.x; d < DC; d += 256)
        o[d] = __float2half(x[d] * inv * (1.f + s[d]));
}

#define L2_10K 13.287712379549449f   // log2(10000)

__global__ void rope_q_kernel(const float* __restrict__ qkv, __half* __restrict__ qout) {
    int head = blockIdx.x;
    int bt = head >> 3, n = head & 7;
    int t = bt & 1023;
    int i = threadIdx.x;
    float rad = (float)t * exp2f((float)i * (-L2_10K / 128.f));
    float s, c;
    sincosf(rad, &s, &c);
    size_t base = (size_t)bt * QKVW + (size_t)n * HC;
    float x1 = qkv[base + i], x2 = qkv[base + 128 + i];
    const float sc = 0.0625f;
    size_t ob = (size_t)head * HC;
    qout[ob + i]       = __float2half((x1 * c - x2 * s) * sc);
    qout[ob + 128 + i] = __float2half((x2 * c + x1 * s) * sc);
}

__global__ void rope_k_kernel(const float* __restrict__ qkv, __half* __restrict__ kd) {
    int bt = blockIdx.x;
    int t = bt & 1023;
    int i = threadIdx.x;
    float rad = (float)t * exp2f((float)i * (-L2_10K / 128.f));
    float s, c;
    sincosf(rad, &s, &c);
    size_t base = (size_t)bt * QKVW + NHD;
    float x1 = qkv[base + i], x2 = qkv[base + 128 + i];
    size_t ob = (size_t)bt * HC;
    kd[ob + i]       = __float2half(x1 * c - x2 * s);
    kd[ob + 128 + i] = __float2half(x2 * c + x1 * s);
}

__global__ void vT_kernel(const float* __restrict__ qkv, __half* __restrict__ vT) {
    __shared__ float tile[32][33];
    int b = blockIdx.z;
    int t0 = blockIdx.x * 32, h0 = blockIdx.y * 32;
    int tx = threadIdx.x, ty = threadIdx.y;
    #pragma unroll
    for (int i = 0; i < 4; i++) {
        int t = t0 + ty + i * 8;
        tile[ty + i * 8][tx] = qkv[((size_t)b * TC + t) * QKVW + NHD + HC + h0 + tx];
    }
    __syncthreads();
    #pragma unroll
    for (int i = 0; i < 4; i++) {
        int h = h0 + ty + i * 8;
        vT[((size_t)b * HC + h) * TC + t0 + tx] = __float2half(tile[tx][ty + i * 8]);
    }
}

// row softmax with valid-span bounds (masked S never read; P tail zeros
// only up to what the AV tile reads).
__global__ void softmax_kernel(const float* __restrict__ S, __half* __restrict__ P) {
    int row = blockIdx.x;
    int tt = (row & (MROWS - 1)) >> 3;
    int Lv = max(T0C, tt + 1);
    int Lw = (max(T0C, (tt & ~15) + 16) + 63) & ~63;
    const float* srow = S + (size_t)row * TC;
    __half* prow = P + (size_t)row * TC;
    int tid = threadIdx.x;
    float4 v[2];
    #pragma unroll
    for (int q = 0; q < 2; q++) {
        int j = q * 512 + tid * 4;
        if (j < Lw) {
            if (j + 4 <= Lv) {
                v[q] = *(const float4*)&srow[j];
            } else {
                float t4[4];
                #pragma unroll
                for (int k = 0; k < 4; k++)
                    t4[k] = (j + k < Lv) ? srow[j + k] : -3.4e38f;
                v[q] = make_float4(t4[0], t4[1], t4[2], t4[3]);
            }
        } else {
            v[q] = make_float4(-3.4e38f, -3.4e38f, -3.4e38f, -3.4e38f);
        }
    }
    float m = fmaxf(fmaxf(v[0].x, v[0].y), fmaxf(v[0].z, v[0].w));
    m = fmaxf(m, fmaxf(fmaxf(v[1].x, v[1].y), fmaxf(v[1].z, v[1].w)));
    __shared__ float red[4];
    #pragma unroll
    for (int o = 16; o; o >>= 1) m = fmaxf(m, __shfl_xor_sync(0xffffffffu, m, o));
    if ((tid & 31) == 0) red[tid >> 5] = m;
    __syncthreads();
    m = fmaxf(fmaxf(red[0], red[1]), fmaxf(red[2], red[3]));
    float l = 0.f;
    #pragma unroll
    for (int q = 0; q < 2; q++) {
        float* e = &v[q].x;
        #pragma unroll
        for (int i = 0; i < 4; i++) {
            float p = __expf(fmaxf(e[i] - m, -80.f));
            e[i] = p;
            l += p;
        }
    }
    #pragma unroll
    for (int o = 16; o; o >>= 1) l += __shfl_xor_sync(0xffffffffu, l, o);
    if ((tid & 31) == 0) red[tid >> 5] = l;
    __syncthreads();
    l = red[0] + red[1] + red[2] + red[3];
    float inv = 1.f / l;
    #pragma unroll
    for (int q = 0; q < 2; q++) {
        int j = q * 512 + tid * 4;
        if (j < Lw) {
            __half2 h0 = __floats2half2_rn(v[q].x * inv, v[q].y * inv);
            __half2 h1 = __floats2half2_rn(v[q].z * inv, v[q].w * inv);
            uint2 u = {h2u(h0), h2u(h1)};
            *(uint2*)&prow[j] = u;
        }
    }
}

// ================= launch =================
extern "C" void kernel_launch(void* const* d_in, const int* in_sizes, int n_in,
                              void* d_out, int out_size) {
    const float* x0  = (const float*)d_in[0];
    const float* x1  = (const float*)d_in[1];
    const float* qw0 = (const float*)d_in[4];
    const float* kw0 = (const float*)d_in[5];
    const float* vw0 = (const float*)d_in[6];
    const float* ow0 = (const float*)d_in[7];
    const float* gw0 = (const float*)d_in[8];
    const float* uw0 = (const float*)d_in[9];
    const float* dw0 = (const float*)d_in[10];
    const float* pa0 = (const float*)d_in[11];
    const float* pf0 = (const float*)d_in[12];
    const float* qw1 = (const float*)d_in[13];
    const float* kw1 = (const float*)d_in[14];
    const float* vw1 = (const float*)d_in[15];
    const float* ow1 = (const float*)d_in[16];
    const float* gw1 = (const float*)d_in[17];
    const float* uw1 = (const float*)d_in[18];
    const float* dw1 = (const float*)d_in[19];
    const float* pa1 = (const float*)d_in[20];
    const float* pf1 = (const float*)d_in[21];

    __half *qwh, *kwh, *vwh, *owh, *gwh, *uwh, *dwh;
    __half *preh, *qhh, *kdhh, *vTh, *Ph, *ench, *hidh, *guh;
    float *qkvf, *S, *resid;
    cudaGetSymbolAddress((void**)&qwh, g_qwh);
    cudaGetSymbolAddress((void**)&kwh, g_kwh);
    cudaGetSymbolAddress((void**)&vwh, g_vwh);
    cudaGetSymbolAddress((void**)&owh, g_owh);
    cudaGetSymbolAddress((void**)&gwh, g_gwh);
    cudaGetSymbolAddress((void**)&uwh, g_uwh);
    cudaGetSymbolAddress((void**)&dwh, g_dwh);
    cudaGetSymbolAddress((void**)&preh, g_preh);
    cudaGetSymbolAddress((void**)&qkvf, g_qkvf);
    cudaGetSymbolAddress((void**)&qhh,  g_qhh);
    cudaGetSymbolAddress((void**)&kdhh, g_kdhh);
    cudaGetSymbolAddress((void**)&vTh,  g_vTh);
    cudaGetSymbolAddress((void**)&S,    g_S);
    cudaGetSymbolAddress((void**)&Ph,   g_Ph);
    cudaGetSymbolAddress((void**)&ench, g_ench);
    cudaGetSymbolAddress((void**)&resid, g_resid);
    cudaGetSymbolAddress((void**)&hidh, g_hidh);
    cudaGetSymbolAddress((void**)&guh,  g_guh);

    const int SMEMH = NSTAGE * STGH * 2;    // 110592
    const int SMEMG = NSTAGE * STGG * 2;    // 165888
    cudaFuncSetAttribute(mma_gemm<1>, cudaFuncAttributeMaxDynamicSharedMemorySize, SMEMH);
    cudaFuncSetAttribute(mma_gemm<2>, cudaFuncAttributeMaxDynamicSharedMemorySize, SMEMH);
    cudaFuncSetAttribute(mma_gemm<6>, cudaFuncAttributeMaxDynamicSharedMemorySize, SMEMH);
    cudaFuncSetAttribute(mma_gemm<7>, cudaFuncAttributeMaxDynamicSharedMemorySize, SMEMH);
    cudaFuncSetAttribute(mma_gemm<8>, cudaFuncAttributeMaxDynamicSharedMemorySize, SMEMH);
    cudaFuncSetAttribute(ffn_gateup, cudaFuncAttributeMaxDynamicSharedMemorySize, SMEMG);

    static cudaStream_t s_aux = nullptr;
    static cudaEvent_t ev_fork = nullptr, ev_join = nullptr;
    if (s_aux == nullptr) {
        cudaStreamCreateWithFlags(&s_aux, cudaStreamNonBlocking);
        cudaEventCreateWithFlags(&ev_fork, cudaEventDisableTiming);
        cudaEventCreateWithFlags(&ev_join, cudaEventDisableTiming);
    }

    // ---- fork: big FFN weight cvt (gw/uw/dw) on aux stream ----
    cudaEventRecord(ev_fork, 0);
    cudaStreamWaitEvent(s_aux, ev_fork, 0);
    {
        CvtArgsN<6> a;
        const float* srcs[6] = {gw0, gw1, uw0, uw1, dw0, dw1};
        __half* dsts[6] = {gwh, gwh + (size_t)FC * DC,
                           uwh, uwh + (size_t)FC * DC,
                           dwh, dwh + (size_t)DC * FC};
        for (int r = 0; r < 6; r++) {
            a.s[r] = (const float4*)srcs[r];
            a.d[r] = (uint2*)dsts[r];
            a.sz[r] = G4;
        }
        size_t tot = 6 * G4;
        cvt_n<6><<<(unsigned)((tot + 255) / 256), 256, 0, s_aux>>>(a);
    }
    cudaEventRecord(ev_join, s_aux);

    // ---- main stream: small QKV/O weight cvt ----
    {
        CvtArgsN<8> a;
        const float* srcs[8] = {qw0, qw1, kw0, kw1, vw0, vw1, ow0, ow1};
        __half* dsts[8] = {qwh, qwh + (size_t)NHD * DC,
                           kwh, kwh + (size_t)HC * DC,
                           vwh, vwh + (size_t)HC * DC,
                           owh, owh + (size_t)DC * NHD};
        size_t szs[8] = {Q4, Q4, KV4, KV4, KV4, KV4, Q4, Q4};
        for (int r = 0; r < 8; r++) {
            a.s[r] = (const float4*)srcs[r];
            a.d[r] = (uint2*)dsts[r];
            a.sz[r] = szs[r];
        }
        size_t tot = 4 * Q4 + 4 * KV4;
        cvt_n<8><<<(unsigned)((tot + 255) / 256), 256>>>(a);
    }

    // 1. pre = RMSNorm(x) -> fp16
    rms_seg_kernel<<<BB * TC, 256>>>(x0, x1, pa0, pa1, preh);
    // 2. fused QKV -> fp32
    mma_gemm<6><<<dim3(32, 20), 256, SMEMH>>>(preh,
        qwh, qwh + (size_t)NHD * DC, kwh, kwh + (size_t)HC * DC,
        vwh, vwh + (size_t)HC * DC,
        qkvf, QKVW, DC, nullptr, nullptr, nullptr);
    // 3. RoPE -> fp16, V transpose -> fp16
    rope_q_kernel<<<BB * TC * NQ, 128>>>(qkvf, qhh);
    rope_k_kernel<<<BB * TC, 128>>>(qkvf, kdhh);
    vT_kernel<<<dim3(TC / 32, HC / 32, BB), dim3(32, 8)>>>(qkvf, vTh);
    // 4a. scores (fp16 MMA, fp32 out); fully-masked tiles skipped
    mma_gemm<7><<<dim3(MROWS / 128, TC / 128, BB), 256, SMEMH>>>(
        qhh, kdhh, nullptr, nullptr, nullptr, nullptr, nullptr,
        S, TC, HC, nullptr, nullptr, nullptr);
    // 4b. bounded softmax -> fp16 probs
    softmax_kernel<<<BB * MROWS, 128>>>(S, Ph);
    // 4c. enc = P @ vT.T -> fp16 (K-loop truncated to valid span)
    mma_gemm<8><<<dim3(MROWS / 128, HC / 128, BB), 256, SMEMH>>>(
        Ph, vTh, nullptr, nullptr, nullptr, nullptr, nullptr,
        ench, HC, TC, nullptr, nullptr, nullptr);
    // 5. O-proj + residual -> fp32 resid
    mma_gemm<1><<<dim3(32, 16), 256, SMEMH>>>(ench,
        owh, owh + (size_t)DC * NHD, nullptr, nullptr, nullptr, nullptr,
        resid, DC, NHD, x0, x1, nullptr);
    // 6. hid = RMSNorm(resid) -> fp16
    rms_cont_kernel<<<BB * TC, 256>>>(resid, pf0, pf1, hidh);

    // ---- join: FFN weights must be converted before gate/up/down ----
    cudaStreamWaitEvent(0, ev_join, 0);

    // 7+8. fused gate+up: gu = gelu(hid@gw.T) * (hid@uw.T) -> fp16
    ffn_gateup<<<dim3(32, 128), 256, SMEMG>>>(hidh,
        gwh, gwh + (size_t)FC * DC, uwh, uwh + (size_t)FC * DC, guh);
    // 9. down-proj + residual -> segmented fp32 d_out
    mma_gemm<2><<<dim3(32, 16), 256, SMEMH>>>(guh,
        dwh, dwh + (size_t)DC * FC, nullptr, nullptr, nullptr, nullptr,
        d_out, DC, FC, nullptr, nullptr, resid);
}

// round 16
// speedup vs baseline: 1.0250x; 1.0250x over previous
#include <cuda_runtime.h>
#include <cuda_fp16.h>
#include <cstdint>
#include <cstddef>

#define BB 4
#define T0C 256
#define T1C 768
#define TC 1024
#define DC 2048
#define NQ 8
#define HC 256
#define FC 16384
#define NHD 2048
#define QKVW 2560
#define MROWS 8192
#define NEGC (-2.3819763e+38f)

// ---------------- fp16 weights ----------------
__device__ __align__(16) __half g_qwh[(size_t)2*NHD*DC];
__device__ __align__(16) __half g_kwh[(size_t)2*HC*DC];
__device__ __align__(16) __half g_vwh[(size_t)2*HC*DC];
__device__ __align__(16) __half g_owh[(size_t)2*DC*NHD];
__device__ __align__(16) __half g_gwh[(size_t)2*FC*DC];
__device__ __align__(16) __half g_uwh[(size_t)2*FC*DC];
__device__ __align__(16) __half g_dwh[(size_t)2*DC*FC];

// ---------------- activations ----------------
__device__ __align__(16) __half g_preh[(size_t)BB*TC*DC];
__device__ float g_qkvf [(size_t)BB*TC*QKVW];
__device__ __align__(16) __half g_qhh [(size_t)BB*TC*NHD];
__device__ __align__(16) __half g_kdhh[(size_t)BB*TC*HC];
__device__ __align__(16) __half g_vTh [(size_t)BB*HC*TC];
__device__ float g_S    [(size_t)BB*MROWS*TC];
__device__ __align__(16) __half g_Ph  [(size_t)BB*MROWS*TC];
__device__ __align__(16) __half g_ench[(size_t)BB*TC*NHD];
__device__ float g_resid[(size_t)BB*TC*DC];
__device__ __align__(16) __half g_hidh[(size_t)BB*TC*DC];
__device__ __align__(16) __half g_guh [(size_t)BB*TC*FC];

__device__ __forceinline__ uint32_t smem_u32(const void* p) {
    uint32_t a;
    asm("{ .reg .u64 t; cvta.to.shared.u64 t, %1; cvt.u32.u64 %0, t; }" : "=r"(a) : "l"(p));
    return a;
}
__device__ __forceinline__ void cp16(uint32_t dst, const void* src) {
    asm volatile("cp.async.ca.shared.global [%0], [%1], 16;" :: "r"(dst), "l"(src));
}
#define CP_COMMIT() asm volatile("cp.async.commit_group;" ::: "memory")
#define CP_WAIT(n)  asm volatile("cp.async.wait_group %0;" :: "n"(n) : "memory")

__device__ __forceinline__ void ldsm4(uint32_t* r, uint32_t addr) {
    asm volatile("ldmatrix.sync.aligned.m8n8.x4.shared.b16 {%0,%1,%2,%3}, [%4];"
        : "=r"(r[0]), "=r"(r[1]), "=r"(r[2]), "=r"(r[3]) : "r"(addr));
}
__device__ __forceinline__ void mma16(float* d, const uint32_t* a, const uint32_t* b) {
    asm volatile(
        "mma.sync.aligned.m16n8k16.row.col.f32.f16.f16.f32 "
        "{%0,%1,%2,%3}, {%4,%5,%6,%7}, {%8,%9}, {%0,%1,%2,%3};"
        : "+f"(d[0]), "+f"(d[1]), "+f"(d[2]), "+f"(d[3])
        : "r"(a[0]), "r"(a[1]), "r"(a[2]), "r"(a[3]), "r"(b[0]), "r"(b[1]));
}
__device__ __forceinline__ float gelu_tanh(float x) {
    float x3 = x * x * x;
    return 0.5f * x * (1.f + tanhf(0.7978845608028654f * (x + 0.044715f * x3)));
}
__device__ __forceinline__ uint32_t h2u(__half2 h) { return *(uint32_t*)&h; }

// ================= fp16 cp.async multistage GEMM (4 warps, 64x64 warp tile) =================
// R14-proven config: CTA 128x128, 4 warps, K-chunk 64, 3 stages, 1 barrier/chunk,
// tail-sound commits, ldmatrix fragments.
// MODE 1: fp32 acc + X(seg) -> resid    MODE 2: fp32 acc + Radd -> scattered d_out
// MODE 6: fused QKV -> fp32 (y: 0-15 qw, 16-17 kw, 18-19 vw)
// MODE 7: fp32 scores (z=batch); fully-masked tiles skipped (no writes)
// MODE 8: fp16 enc (z=batch); K-loop truncated to valid span (tail P is zero)
#define SROWH 72
#define NSTAGE 3
#define STGH (2 * 128 * SROWH)

template <int MODE>
__global__ void __launch_bounds__(128, 2)
mma_gemm(const __half* __restrict__ A,
         const __half* __restrict__ W0, const __half* __restrict__ W1,
         const __half* __restrict__ K0, const __half* __restrict__ K1,
         const __half* __restrict__ V0, const __half* __restrict__ V1,
         void* __restrict__ Cv, int Nout, int Kdim,
         const float* __restrict__ X0, const float* __restrict__ X1,
         const float* __restrict__ Radd) {
    extern __shared__ __half smh[];
    uint32_t sbase = smem_u32(smh);
    int tid = threadIdx.x, wid = tid >> 5, lane = tid & 31;
    int warp_m = wid & 1, warp_n = wid >> 1;
    int rm0 = blockIdx.x * 128;
    int rn0 = blockIdx.y * 128;
    int z = blockIdx.z;

    if (MODE == 7) {
        int tt_max = (rm0 >> 3) + 15;
        if (rn0 >= T0C && rn0 > tt_max) return;   // fully masked tile
    }

    const __half* Wa; const __half* Wb; int wr0 = rn0;
    if (MODE == 6) {
        if (blockIdx.y < 16)      { Wa = W0; Wb = W1; wr0 = blockIdx.y * 128; }
        else if (blockIdx.y < 18) { Wa = K0; Wb = K1; wr0 = (blockIdx.y - 16) * 128; }
        else                      { Wa = V0; Wb = V1; wr0 = (blockIdx.y - 18) * 128; }
    } else { Wa = W0; Wb = W1; }

    const __half* W;
    float* Cf = (float*)Cv;
    __half* Ch = (__half*)Cv;
    if (MODE == 7) {
        A += (size_t)z * MROWS * HC;
        W = W0 + (size_t)z * TC * HC;
        Cf += (size_t)z * MROWS * TC;
    } else if (MODE == 8) {
        A += (size_t)z * MROWS * TC;
        W = W0 + (size_t)z * HC * TC;
        Ch += (size_t)z * MROWS * HC;
    } else {
        W = ((rm0 & 1023) < T0C) ? Wa : Wb;
    }

    const uint32_t a_off =
        (uint32_t)(((warp_m * 64 + (lane & 15)) * SROWH + (lane >> 4) * 8) * 2);
    const uint32_t b_off =
        (uint32_t)((128 * SROWH +
                    (warp_n * 64 + (lane & 7) + ((lane >> 4) & 1) * 8) * SROWH +
                    ((lane >> 3) & 1) * 8) * 2);

    float acc[4][8][4];
    #pragma unroll
    for (int t = 0; t < 4; t++)
        #pragma unroll
        for (int j = 0; j < 8; j++)
            #pragma unroll
            for (int e = 0; e < 4; e++) acc[t][j][e] = 0.f;

    auto issue = [&](int c) {
        int stg = c - (c / NSTAGE) * NSTAGE;
        uint32_t sb = sbase + stg * (STGH * 2);
        int kb = c << 6;
        #pragma unroll
        for (int it = 0; it < 16; it++) {
            int idx = it * 128 + tid;
            int row = (idx >> 3) & 127;
            int sg = (idx & 7) << 3;
            if (idx < 1024)
                cp16(sb + (uint32_t)(row * SROWH + sg) * 2,
                     A + (size_t)(rm0 + row) * Kdim + kb + sg);
            else
                cp16(sb + (uint32_t)(128 * SROWH + row * SROWH + sg) * 2,
                     W + (size_t)(wr0 + row) * Kdim + kb + sg);
        }
    };

    auto compute = [&](int stg) {
        uint32_t sb = sbase + stg * (STGH * 2);
        #pragma unroll
        for (int ks = 0; ks < 4; ks++) {
            uint32_t af[4][4], bf[8][2];
            #pragma unroll
            for (int t = 0; t < 4; t++)
                ldsm4(af[t], sb + a_off + (uint32_t)((t * 16 * SROWH + ks * 16) * 2));
            #pragma unroll
            for (int p = 0; p < 4; p++)
                ldsm4(&bf[2 * p][0], sb + b_off + (uint32_t)((p * 16 * SROWH + ks * 16) * 2));
            #pragma unroll
            for (int t = 0; t < 4; t++)
                #pragma unroll
                for (int j = 0; j < 8; j++)
                    mma16(acc[t][j], af[t], bf[j]);
        }
    };

    int nch;
    if (MODE == 8) {
        int kmax = max(T0C, (rm0 >> 3) + 16);
        nch = (kmax + 63) >> 6;
    } else {
        nch = Kdim >> 6;
    }

    issue(0); CP_COMMIT();
    issue(1); CP_COMMIT();
    int stg = 0;
    for (int c = 0; c < nch; c++) {
        CP_WAIT(1);
        __syncthreads();
        compute(stg);
        if (++stg == NSTAGE) stg = 0;
        int nx = c + NSTAGE - 1;
        if (nx < nch) issue(nx);
        CP_COMMIT();
    }

    // ---------------- epilogue ----------------
    #pragma unroll
    for (int t = 0; t < 4; t++) {
        #pragma unroll
        for (int j = 0; j < 8; j++) {
            int c = rn0 + warp_n * 64 + j * 8 + (lane & 3) * 2;
            #pragma unroll
            for (int h = 0; h < 2; h++) {
                int r = rm0 + warp_m * 64 + t * 16 + (lane >> 2) + h * 8;
                float v0 = acc[t][j][h * 2 + 0];
                float v1 = acc[t][j][h * 2 + 1];
                if (MODE == 6) {
                    float2 v = {v0, v1};
                    *(float2*)&Cf[(size_t)r * Nout + c] = v;
                } else if (MODE == 8) {
                    *(__half2*)&Ch[(size_t)r * Nout + c] = __floats2half2_rn(v0, v1);
                } else if (MODE == 1) {
                    int b = r >> 10, tt = r & 1023;
                    const float* xp = (tt < T0C)
                        ? X0 + ((size_t)b * T0C + tt) * DC + c
                        : X1 + ((size_t)b * T1C + (tt - T0C)) * DC + c;
                    float2 xv = *(const float2*)xp;
                    float2 v = {v0 + xv.x, v1 + xv.y};
                    *(float2*)&Cf[(size_t)r * DC + c] = v;
                } else if (MODE == 2) {
                    float2 rv = *(const float2*)&Radd[(size_t)r * DC + c];
                    int b = r >> 10, tt = r & 1023;
                    size_t dst = (tt < T0C)
                        ? ((size_t)b * T0C + tt) * DC + c
                        : (size_t)BB * T0C * DC + ((size_t)b * T1C + (tt - T0C)) * DC + c;
                    float2 v = {v0 + rv.x, v1 + rv.y};
                    *(float2*)&Cf[dst] = v;
                } else if (MODE == 7) {
                    float2 v = {v0, v1};
                    *(float2*)&Cf[(size_t)r * TC + c] = v;
                }
            }
        }
    }
}

// ================= fused gate+up FFN kernel (ldmatrix, 1 barrier/chunk) =================
#define STGG (384 * SROWH)

__global__ void __launch_bounds__(256, 1)
ffn_gateup(const __half* __restrict__ A,
           const __half* __restrict__ G0, const __half* __restrict__ G1,
           const __half* __restrict__ U0, const __half* __restrict__ U1,
           __half* __restrict__ Cg) {
    extern __shared__ __half smh[];
    uint32_t sbase = smem_u32(smh);
    int tid = threadIdx.x, wid = tid >> 5, lane = tid & 31;
    int w4 = wid & 3;
    int is_up = wid >> 2;
    int warp_m = w4 & 1, warp_n = w4 >> 1;
    int rm0 = blockIdx.x * 128;
    int rn0 = blockIdx.y * 128;
    bool seg1 = (rm0 & 1023) >= T0C;
    const __half* Wg = seg1 ? G1 : G0;
    const __half* Wu = seg1 ? U1 : U0;

    const uint32_t a_off =
        (uint32_t)(((warp_m * 64 + (lane & 15)) * SROWH + (lane >> 4) * 8) * 2);
    const uint32_t b_off =
        (uint32_t)(((128 + is_up * 128) * SROWH +
                    (warp_n * 64 + (lane & 7) + ((lane >> 4) & 1) * 8) * SROWH +
                    ((lane >> 3) & 1) * 8) * 2);

    float acc[4][8][4];
    #pragma unroll
    for (int t = 0; t < 4; t++)
        #pragma unroll
        for (int j = 0; j < 8; j++)
            #pragma unroll
            for (int e = 0; e < 4; e++) acc[t][j][e] = 0.f;

    auto issue = [&](int c) {
        int stg = c - (c / NSTAGE) * NSTAGE;
        uint32_t sb = sbase + stg * (STGG * 2);
        int kb = c << 6;
        #pragma unroll
        for (int it = 0; it < 12; it++) {
            int idx = it * 256 + tid;
            int row = idx >> 3;
            int sg = (idx & 7) << 3;
            const __half* src;
            if (row < 128)
                src = A + (size_t)(rm0 + row) * DC + kb + sg;
            else if (row < 256)
                src = Wg + (size_t)(rn0 + row - 128) * DC + kb + sg;
            else
                src = Wu + (size_t)(rn0 + row - 256) * DC + kb + sg;
            cp16(sb + (uint32_t)(row * SROWH + sg) * 2, src);
        }
    };

    auto compute = [&](int stg) {
        uint32_t sb = sbase + stg * (STGG * 2);
        #pragma unroll
        for (int ks = 0; ks < 4; ks++) {
            uint32_t af[4][4], bf[8][2];
            #pragma unroll
            for (int t = 0; t < 4; t++)
                ldsm4(af[t], sb + a_off + (uint32_t)((t * 16 * SROWH + ks * 16) * 2));
            #pragma unroll
            for (int p = 0; p < 4; p++)
                ldsm4(&bf[2 * p][0], sb + b_off + (uint32_t)((p * 16 * SROWH + ks * 16) * 2));
            #pragma unroll
            for (int t = 0; t < 4; t++)
                #pragma unroll
                for (int j = 0; j < 8; j++)
                    mma16(acc[t][j], af[t], bf[j]);
        }
    };

    const int nch = DC >> 6;
    issue(0); CP_COMMIT();
    issue(1); CP_COMMIT();
    int stg = 0;
    for (int c = 0; c < nch; c++) {
        CP_WAIT(1);
        __syncthreads();
        compute(stg);
        if (++stg == NSTAGE) stg = 0;
        int nx = c + NSTAGE - 1;
        if (nx < nch) issue(nx);
        CP_COMMIT();
    }

    CP_WAIT(0);
    __syncthreads();

    float* gt = (float*)smh;
    if (!is_up) {
        #pragma unroll
        for (int t = 0; t < 4; t++)
            #pragma unroll
            for (int j = 0; j < 8; j++) {
                int cl = warp_n * 64 + j * 8 + (lane & 3) * 2;
                #pragma unroll
                for (int h = 0; h < 2; h++) {
                    int rl = warp_m * 64 + t * 16 + (lane >> 2) + h * 8;
                    gt[rl * 132 + cl]     = gelu_tanh(acc[t][j][h * 2 + 0]);
                    gt[rl * 132 + cl + 1] = gelu_tanh(acc[t][j][h * 2 + 1]);
                }
            }
    }
    __syncthreads();
    if (is_up) {
        #pragma unroll
        for (int t = 0; t < 4; t++)
            #pragma unroll
            for (int j = 0; j < 8; j++) {
                int cl = warp_n * 64 + j * 8 + (lane & 3) * 2;
                int c = rn0 + cl;
                #pragma unroll
                for (int h = 0; h < 2; h++) {
                    int rl = warp_m * 64 + t * 16 + (lane >> 2) + h * 8;
                    int r = rm0 + rl;
                    float g0 = gt[rl * 132 + cl];
                    float g1 = gt[rl * 132 + cl + 1];
                    *(__half2*)&Cg[(size_t)r * FC + c] =
                        __floats2half2_rn(g0 * acc[t][j][h * 2 + 0],
                                          g1 * acc[t][j][h * 2 + 1]);
                }
            }
    }
}

// ================= split weight conversion =================
template <int NR>
struct CvtArgsN {
    const float4* s[NR];
    uint2* d[NR];
    size_t sz[NR];
};

template <int NR>
__global__ void cvt_n(CvtArgsN<NR> a) {
    size_t i = (size_t)blockIdx.x * 256 + threadIdx.x;
    size_t base = 0;
    #pragma unroll
    for (int r = 0; r < NR; r++) {
        if (i < base + a.sz[r]) {
            size_t k = i - base;
            float4 v = a.s[r][k];
            __half2 h0 = __floats2half2_rn(v.x, v.y);
            __half2 h1 = __floats2half2_rn(v.z, v.w);
            uint2 u = {h2u(h0), h2u(h1)};
            a.d[r][k] = u;
            return;
        }
        base += a.sz[r];
    }
}

#define Q4 ((size_t)NHD * DC / 4)
#define KV4 ((size_t)HC * DC / 4)
#define G4 ((size_t)FC * DC / 4)

// ================= elementwise =================
__device__ __forceinline__ float warp_sum(float v) {
    #pragma unroll
    for (int o = 16; o; o >>= 1) v += __shfl_down_sync(0xffffffffu, v, o);
    return v;
}

__global__ void rms_seg_kernel(const float* __restrict__ x0, const float* __restrict__ x1,
                               const float* __restrict__ s0, const float* __restrict__ s1,
                               __half* __restrict__ out) {
    int row = blockIdx.x;
    int b = row >> 10, t = row & 1023;
    const float* x; const float* s;
    if (t < T0C) { x = x0 + ((size_t)b*T0C + t)*DC; s = s0; }
    else         { x = x1 + ((size_t)b*T1C + (t - T0C))*DC; s = s1; }
    float ss = 0.f;
    for (int d = threadIdx.x; d < DC; d += 256) { float v = x[d]; ss += v*v; }
    __shared__ float red[8];
    ss = warp_sum(ss);
    if ((threadIdx.x & 31) == 0) red[threadIdx.x >> 5] = ss;
    __syncthreads();
    if (threadIdx.x < 8) {
        float v = red[threadIdx.x];
        #pragma unroll
        for (int o = 4; o; o >>= 1) v += __shfl_down_sync(0xffu, v, o);
        if (threadIdx.x == 0) red[0] = v;
    }
    __syncthreads();
    float inv = rsqrtf(red[0] * (1.f / DC) + 1e-6f);
    __half* o = out + (size_t)row * DC;
    for (int d = threadIdx.x; d < DC; d += 256)
        o[d] = __float2half(x[d] * inv * (1.f + s[d]));
}

__global__ void rms_cont_kernel(const float* __restrict__ xin,
                                const float* __restrict__ s0, const float* __restrict__ s1,
                                __half* __restrict__ out) {
    int row = blockIdx.x;
    int t = row & 1023;
    const float* x = xin + (size_t)row * DC;
    const float* s = (t < T0C) ? s0 : s1;
    float ss = 0.f;
    for (int d = threadIdx.x; d < DC; d += 256) { float v = x[d]; ss += v*v; }
    __shared__ float red[8];
    ss = warp_sum(ss);
    if ((threadIdx.x & 31) == 0) red[threadIdx.x >> 5] = ss;
    __syncthreads();
    if (threadIdx.x < 8) {
        float v = red[threadIdx.x];
        #pragma unroll
        for (int o = 4; o; o >>= 1) v += __shfl_down_sync(0xffu, v, o);
        if (threadIdx.x == 0) red[0] = v;
    }
    __syncthreads();
    float inv = rsqrtf(red[0] * (1.f / DC) + 1e-6f);
    __half* o = out + (size_t)row * DC;
    for (int d = threadIdx.x; d < DC; d += 256)
        o[d] = __float2half(x[d] * inv * (1.f + s[d]));
}

#define L2_10K 13.287712379549449f   // log2(10000)

__global__ void rope_q_kernel(const float* __restrict__ qkv, __half* __restrict__ qout) {
    int head = blockIdx.x;
    int bt = head >> 3, n = head & 7;
    int t = bt & 1023;
    int i = threadIdx.x;
    float rad = (float)t * exp2f((float)i * (-L2_10K / 128.f));
    float s, c;
    sincosf(rad, &s, &c);
    size_t base = (size_t)bt * QKVW + (size_t)n * HC;
    float x1 = qkv[base + i], x2 = qkv[base + 128 + i];
    const float sc = 0.0625f;
    size_t ob = (size_t)head * HC;
    qout[ob + i]       = __float2half((x1 * c - x2 * s) * sc);
    qout[ob + 128 + i] = __float2half((x2 * c + x1 * s) * sc);
}

__global__ void rope_k_kernel(const float* __restrict__ qkv, __half* __restrict__ kd) {
    int bt = blockIdx.x;
    int t = bt & 1023;
    int i = threadIdx.x;
    float rad = (float)t * exp2f((float)i * (-L2_10K / 128.f));
    float s, c;
    sincosf(rad, &s, &c);
    size_t base = (size_t)bt * QKVW + NHD;
    float x1 = qkv[base + i], x2 = qkv[base + 128 + i];
    size_t ob = (size_t)bt * HC;
    kd[ob + i]       = __float2half(x1 * c - x2 * s);
    kd[ob + 128 + i] = __float2half(x2 * c + x1 * s);
}

__global__ void vT_kernel(const float* __restrict__ qkv, __half* __restrict__ vT) {
    __shared__ float tile[32][33];
    int b = blockIdx.z;
    int t0 = blockIdx.x * 32, h0 = blockIdx.y * 32;
    int tx = threadIdx.x, ty = threadIdx.y;
    #pragma unroll
    for (int i = 0; i < 4; i++) {
        int t = t0 + ty + i * 8;
        tile[ty + i * 8][tx] = qkv[((size_t)b * TC + t) * QKVW + NHD + HC + h0 + tx];
    }
    __syncthreads();
    #pragma unroll
    for (int i = 0; i < 4; i++) {
        int h = h0 + ty + i * 8;
        vT[((size_t)b * HC + h) * TC + t0 + tx] = __float2half(tile[tx][ty + i * 8]);
    }
}

// row softmax with valid-span bounds (masked S never read; P tail zeros
// only up to what the AV tile reads).
__global__ void softmax_kernel(const float* __restrict__ S, __half* __restrict__ P) {
    int row = blockIdx.x;
    int tt = (row & (MROWS - 1)) >> 3;
    int Lv = max(T0C, tt + 1);
    int Lw = (max(T0C, (tt & ~15) + 16) + 63) & ~63;
    const float* srow = S + (size_t)row * TC;
    __half* prow = P + (size_t)row * TC;
    int tid = threadIdx.x;
    float4 v[2];
    #pragma unroll
    for (int q = 0; q < 2; q++) {
        int j = q * 512 + tid * 4;
        if (j < Lw) {
            if (j + 4 <= Lv) {
                v[q] = *(const float4*)&srow[j];
            } else {
                float t4[4];
                #pragma unroll
                for (int k = 0; k < 4; k++)
                    t4[k] = (j + k < Lv) ? srow[j + k] : -3.4e38f;
                v[q] = make_float4(t4[0], t4[1], t4[2], t4[3]);
            }
        } else {
            v[q] = make_float4(-3.4e38f, -3.4e38f, -3.4e38f, -3.4e38f);
        }
    }
    float m = fmaxf(fmaxf(v[0].x, v[0].y), fmaxf(v[0].z, v[0].w));
    m = fmaxf(m, fmaxf(fmaxf(v[1].x, v[1].y), fmaxf(v[1].z, v[1].w)));
    __shared__ float red[4];
    #pragma unroll
    for (int o = 16; o; o >>= 1) m = fmaxf(m, __shfl_xor_sync(0xffffffffu, m, o));
    if ((tid & 31) == 0) red[tid >> 5] = m;
    __syncthreads();
    m = fmaxf(fmaxf(red[0], red[1]), fmaxf(red[2], red[3]));
    float l = 0.f;
    #pragma unroll
    for (int q = 0; q < 2; q++) {
        float* e = &v[q].x;
        #pragma unroll
        for (int i = 0; i < 4; i++) {
            float p = __expf(fmaxf(e[i] - m, -80.f));
            e[i] = p;
            l += p;
        }
    }
    #pragma unroll
    for (int o = 16; o; o >>= 1) l += __shfl_xor_sync(0xffffffffu, l, o);
    if ((tid & 31) == 0) red[tid >> 5] = l;
    __syncthreads();
    l = red[0] + red[1] + red[2] + red[3];
    float inv = 1.f / l;
    #pragma unroll
    for (int q = 0; q < 2; q++) {
        int j = q * 512 + tid * 4;
        if (j < Lw) {
            __half2 h0 = __floats2half2_rn(v[q].x * inv, v[q].y * inv);
            __half2 h1 = __floats2half2_rn(v[q].z * inv, v[q].w * inv);
            uint2 u = {h2u(h0), h2u(h1)};
            *(uint2*)&prow[j] = u;
        }
    }
}

// ================= launch =================
extern "C" void kernel_launch(void* const* d_in, const int* in_sizes, int n_in,
                              void* d_out, int out_size) {
    const float* x0  = (const float*)d_in[0];
    const float* x1  = (const float*)d_in[1];
    const float* qw0 = (const float*)d_in[4];
    const float* kw0 = (const float*)d_in[5];
    const float* vw0 = (const float*)d_in[6];
    const float* ow0 = (const float*)d_in[7];
    const float* gw0 = (const float*)d_in[8];
    const float* uw0 = (const float*)d_in[9];
    const float* dw0 = (const float*)d_in[10];
    const float* pa0 = (const float*)d_in[11];
    const float* pf0 = (const float*)d_in[12];
    const float* qw1 = (const float*)d_in[13];
    const float* kw1 = (const float*)d_in[14];
    const float* vw1 = (const float*)d_in[15];
    const float* ow1 = (const float*)d_in[16];
    const float* gw1 = (const float*)d_in[17];
    const float* uw1 = (const float*)d_in[18];
    const float* dw1 = (const float*)d_in[19];
    const float* pa1 = (const float*)d_in[20];
    const float* pf1 = (const float*)d_in[21];

    __half *qwh, *kwh, *vwh, *owh, *gwh, *uwh, *dwh;
    __half *preh, *qhh, *kdhh, *vTh, *Ph, *ench, *hidh, *guh;
    float *qkvf, *S, *resid;
    cudaGetSymbolAddress((void**)&qwh, g_qwh);
    cudaGetSymbolAddress((void**)&kwh, g_kwh);
    cudaGetSymbolAddress((void**)&vwh, g_vwh);
    cudaGetSymbolAddress((void**)&owh, g_owh);
    cudaGetSymbolAddress((void**)&gwh, g_gwh);
    cudaGetSymbolAddress((void**)&uwh, g_uwh);
    cudaGetSymbolAddress((void**)&dwh, g_dwh);
    cudaGetSymbolAddress((void**)&preh, g_preh);
    cudaGetSymbolAddress((void**)&qkvf, g_qkvf);
    cudaGetSymbolAddress((void**)&qhh,  g_qhh);
    cudaGetSymbolAddress((void**)&kdhh, g_kdhh);
    cudaGetSymbolAddress((void**)&vTh,  g_vTh);
    cudaGetSymbolAddress((void**)&S,    g_S);
    cudaGetSymbolAddress((void**)&Ph,   g_Ph);
    cudaGetSymbolAddress((void**)&ench, g_ench);
    cudaGetSymbolAddress((void**)&resid, g_resid);
    cudaGetSymbolAddress((void**)&hidh, g_hidh);
    cudaGetSymbolAddress((void**)&guh,  g_guh);

    const int SMEMH = NSTAGE * STGH * 2;    // 110592
    const int SMEMG = NSTAGE * STGG * 2;    // 165888
    cudaFuncSetAttribute(mma_gemm<1>, cudaFuncAttributeMaxDynamicSharedMemorySize, SMEMH);
    cudaFuncSetAttribute(mma_gemm<2>, cudaFuncAttributeMaxDynamicSharedMemorySize, SMEMH);
    cudaFuncSetAttribute(mma_gemm<6>, cudaFuncAttributeMaxDynamicSharedMemorySize, SMEMH);
    cudaFuncSetAttribute(mma_gemm<7>, cudaFuncAttributeMaxDynamicSharedMemorySize, SMEMH);
    cudaFuncSetAttribute(mma_gemm<8>, cudaFuncAttributeMaxDynamicSharedMemorySize, SMEMH);
    cudaFuncSetAttribute(ffn_gateup, cudaFuncAttributeMaxDynamicSharedMemorySize, SMEMG);

    static cudaStream_t s_aux = nullptr, s_aux2 = nullptr;
    static cudaEvent_t ev_fork = nullptr, ev_join = nullptr;
    static cudaEvent_t ev_qkv = nullptr, ev_ew = nullptr;
    if (s_aux == nullptr) {
        cudaStreamCreateWithFlags(&s_aux, cudaStreamNonBlocking);
        cudaStreamCreateWithFlags(&s_aux2, cudaStreamNonBlocking);
        cudaEventCreateWithFlags(&ev_fork, cudaEventDisableTiming);
        cudaEventCreateWithFlags(&ev_join, cudaEventDisableTiming);
        cudaEventCreateWithFlags(&ev_qkv, cudaEventDisableTiming);
        cudaEventCreateWithFlags(&ev_ew, cudaEventDisableTiming);
    }

    // ---- fork: big FFN weight cvt (gw/uw/dw) on aux stream ----
    cudaEventRecord(ev_fork, 0);
    cudaStreamWaitEvent(s_aux, ev_fork, 0);
    {
        CvtArgsN<6> a;
        const float* srcs[6] = {gw0, gw1, uw0, uw1, dw0, dw1};
        __half* dsts[6] = {gwh, gwh + (size_t)FC * DC,
                           uwh, uwh + (size_t)FC * DC,
                           dwh, dwh + (size_t)DC * FC};
        for (int r = 0; r < 6; r++) {
            a.s[r] = (const float4*)srcs[r];
            a.d[r] = (uint2*)dsts[r];
            a.sz[r] = G4;
        }
        size_t tot = 6 * G4;
        cvt_n<6><<<(unsigned)((tot + 255) / 256), 256, 0, s_aux>>>(a);
    }
    cudaEventRecord(ev_join, s_aux);

    // ---- main stream: small QKV/O weight cvt ----
    {
        CvtArgsN<8> a;
        const float* srcs[8] = {qw0, qw1, kw0, kw1, vw0, vw1, ow0, ow1};
        __half* dsts[8] = {qwh, qwh + (size_t)NHD * DC,
                           kwh, kwh + (size_t)HC * DC,
                           vwh, vwh + (size_t)HC * DC,
                           owh, owh + (size_t)DC * NHD};
        size_t szs[8] = {Q4, Q4, KV4, KV4, KV4, KV4, Q4, Q4};
        for (int r = 0; r < 8; r++) {
            a.s[r] = (const float4*)srcs[r];
            a.d[r] = (uint2*)dsts[r];
            a.sz[r] = szs[r];
        }
        size_t tot = 4 * Q4 + 4 * KV4;
        cvt_n<8><<<(unsigned)((tot + 255) / 256), 256>>>(a);
    }

    // 1. pre = RMSNorm(x) -> fp16
    rms_seg_kernel<<<BB * TC, 256>>>(x0, x1, pa0, pa1, preh);
    // 2. fused QKV -> fp32
    mma_gemm<6><<<dim3(32, 20), 128, SMEMH>>>(preh,
        qwh, qwh + (size_t)NHD * DC, kwh, kwh + (size_t)HC * DC,
        vwh, vwh + (size_t)HC * DC,
        qkvf, QKVW, DC, nullptr, nullptr, nullptr);

    // ---- fork elementwise: rope_k + vT on s_aux2, rope_q on main ----
    cudaEventRecord(ev_qkv, 0);
    cudaStreamWaitEvent(s_aux2, ev_qkv, 0);
    rope_k_kernel<<<BB * TC, 128, 0, s_aux2>>>(qkvf, kdhh);
    vT_kernel<<<dim3(TC / 32, HC / 32, BB), dim3(32, 8), 0, s_aux2>>>(qkvf, vTh);
    cudaEventRecord(ev_ew, s_aux2);
    rope_q_kernel<<<BB * TC * NQ, 128>>>(qkvf, qhh);
    cudaStreamWaitEvent(0, ev_ew, 0);

    // 4a. scores (fp16 MMA, fp32 out); fully-masked tiles skipped
    mma_gemm<7><<<dim3(MROWS / 128, TC / 128, BB), 128, SMEMH>>>(
        qhh, kdhh, nullptr, nullptr, nullptr, nullptr, nullptr,
        S, TC, HC, nullptr, nullptr, nullptr);
    // 4b. bounded softmax -> fp16 probs
    softmax_kernel<<<BB * MROWS, 128>>>(S, Ph);
    // 4c. enc = P @ vT.T -> fp16 (K-loop truncated to valid span)
    mma_gemm<8><<<dim3(MROWS / 128, HC / 128, BB), 128, SMEMH>>>(
        Ph, vTh, nullptr, nullptr, nullptr, nullptr, nullptr,
        ench, HC, TC, nullptr, nullptr, nullptr);
    // 5. O-proj + residual -> fp32 resid
    mma_gemm<1><<<dim3(32, 16), 128, SMEMH>>>(ench,
        owh, owh + (size_t)DC * NHD, nullptr, nullptr, nullptr, nullptr,
        resid, DC, NHD, x0, x1, nullptr);
    // 6. hid = RMSNorm(resid) -> fp16
    rms_cont_kernel<<<BB * TC, 256>>>(resid, pf0, pf1, hidh);

    // ---- join: FFN weights must be converted before gate/up/down ----
    cudaStreamWaitEvent(0, ev_join, 0);

    // 7+8. fused gate+up: gu = gelu(hid@gw.T) * (hid@uw.T) -> fp16
    ffn_gateup<<<dim3(32, 128), 256, SMEMG>>>(hidh,
        gwh, gwh + (size_t)FC * DC, uwh, uwh + (size_t)FC * DC, guh);
    // 9. down-proj + residual -> segmented fp32 d_out
    mma_gemm<2><<<dim3(32, 16), 128, SMEMH>>>(guh,
        dwh, dwh + (size_t)DC * FC, nullptr, nullptr, nullptr, nullptr,
        d_out, DC, FC, nullptr, nullptr, resid);
}

// round 17
// speedup vs baseline: 1.0253x; 1.0003x over previous
#include <cuda_runtime.h>
#include <cuda_fp16.h>
#include <cstdint>
#include <cstddef>

#define BB 4
#define T0C 256
#define T1C 768
#define TC 1024
#define DC 2048
#define NQ 8
#define HC 256
#define FC 16384
#define NHD 2048
#define QKVW 2560
#define MROWS 8192
#define NEGC (-2.3819763e+38f)

// ---------------- fp16 weights ----------------
__device__ __align__(16) __half g_qwh[(size_t)2*NHD*DC];
__device__ __align__(16) __half g_kwh[(size_t)2*HC*DC];
__device__ __align__(16) __half g_vwh[(size_t)2*HC*DC];
__device__ __align__(16) __half g_owh[(size_t)2*DC*NHD];
__device__ __align__(16) __half g_gwh[(size_t)2*FC*DC];
__device__ __align__(16) __half g_uwh[(size_t)2*FC*DC];
__device__ __align__(16) __half g_dwh[(size_t)2*DC*FC];

// ---------------- activations ----------------
__device__ __align__(16) __half g_preh[(size_t)BB*TC*DC];
__device__ float g_qkvf [(size_t)BB*TC*QKVW];
__device__ __align__(16) __half g_qhh [(size_t)BB*TC*NHD];
__device__ __align__(16) __half g_kdhh[(size_t)BB*TC*HC];
__device__ __align__(16) __half g_vTh [(size_t)BB*HC*TC];
__device__ float g_S    [(size_t)BB*MROWS*TC];
__device__ __align__(16) __half g_Ph  [(size_t)BB*MROWS*TC];
__device__ __align__(16) __half g_ench[(size_t)BB*TC*NHD];
__device__ float g_resid[(size_t)BB*TC*DC];
__device__ __align__(16) __half g_hidh[(size_t)BB*TC*DC];
__device__ __align__(16) __half g_guh [(size_t)BB*TC*FC];

__device__ __forceinline__ uint32_t smem_u32(const void* p) {
    uint32_t a;
    asm("{ .reg .u64 t; cvta.to.shared.u64 t, %1; cvt.u32.u64 %0, t; }" : "=r"(a) : "l"(p));
    return a;
}
__device__ __forceinline__ void cp16(uint32_t dst, const void* src) {
    asm volatile("cp.async.ca.shared.global [%0], [%1], 16;" :: "r"(dst), "l"(src));
}
#define CP_COMMIT() asm volatile("cp.async.commit_group;" ::: "memory")
#define CP_WAIT(n)  asm volatile("cp.async.wait_group %0;" :: "n"(n) : "memory")

__device__ __forceinline__ void ldsm4(uint32_t* r, uint32_t addr) {
    asm volatile("ldmatrix.sync.aligned.m8n8.x4.shared.b16 {%0,%1,%2,%3}, [%4];"
        : "=r"(r[0]), "=r"(r[1]), "=r"(r[2]), "=r"(r[3]) : "r"(addr));
}
__device__ __forceinline__ void mma16(float* d, const uint32_t* a, const uint32_t* b) {
    asm volatile(
        "mma.sync.aligned.m16n8k16.row.col.f32.f16.f16.f32 "
        "{%0,%1,%2,%3}, {%4,%5,%6,%7}, {%8,%9}, {%0,%1,%2,%3};"
        : "+f"(d[0]), "+f"(d[1]), "+f"(d[2]), "+f"(d[3])
        : "r"(a[0]), "r"(a[1]), "r"(a[2]), "r"(a[3]), "r"(b[0]), "r"(b[1]));
}
__device__ __forceinline__ float gelu_tanh(float x) {
    float x3 = x * x * x;
    return 0.5f * x * (1.f + tanhf(0.7978845608028654f * (x + 0.044715f * x3)));
}
__device__ __forceinline__ uint32_t h2u(__half2 h) { return *(uint32_t*)&h; }

// ================= fp16 cp.async multistage GEMM (4 warps, 64x64 warp tile) =================
// CTA 128x128, 4 warps, K-chunk 64, 3 stages, 1 barrier/chunk, tail-sound commits.
// MODE 1: fp32 acc + X(seg) -> resid    MODE 2: fp32 acc + Radd -> scattered d_out
// MODE 6: fused QKV (y: 0-15 qw -> fp32 qkv, 16-17 kw -> fp32 qkv,
//                    18-19 vw -> fp16 vT DIRECT transposed write)
// MODE 7: fp32 scores (z=batch); fully-masked tiles skipped (no writes)
// MODE 8: fp16 enc (z=batch); K-loop truncated to valid span (tail P is zero)
#define SROWH 72
#define NSTAGE 3
#define STGH (2 * 128 * SROWH)

template <int MODE>
__global__ void __launch_bounds__(128, 2)
mma_gemm(const __half* __restrict__ A,
         const __half* __restrict__ W0, const __half* __restrict__ W1,
         const __half* __restrict__ K0, const __half* __restrict__ K1,
         const __half* __restrict__ V0, const __half* __restrict__ V1,
         void* __restrict__ Cv, int Nout, int Kdim,
         const float* __restrict__ X0, const float* __restrict__ X1,
         const float* __restrict__ Radd,
         __half* __restrict__ Vt) {
    extern __shared__ __half smh[];
    uint32_t sbase = smem_u32(smh);
    int tid = threadIdx.x, wid = tid >> 5, lane = tid & 31;
    int warp_m = wid & 1, warp_n = wid >> 1;
    int rm0 = blockIdx.x * 128;
    int rn0 = blockIdx.y * 128;
    int z = blockIdx.z;

    if (MODE == 7) {
        int tt_max = (rm0 >> 3) + 15;
        if (rn0 >= T0C && rn0 > tt_max) return;   // fully masked tile
    }

    const __half* Wa; const __half* Wb; int wr0 = rn0;
    if (MODE == 6) {
        if (blockIdx.y < 16)      { Wa = W0; Wb = W1; wr0 = blockIdx.y * 128; }
        else if (blockIdx.y < 18) { Wa = K0; Wb = K1; wr0 = (blockIdx.y - 16) * 128; }
        else                      { Wa = V0; Wb = V1; wr0 = (blockIdx.y - 18) * 128; }
    } else { Wa = W0; Wb = W1; }

    const __half* W;
    float* Cf = (float*)Cv;
    __half* Ch = (__half*)Cv;
    if (MODE == 7) {
        A += (size_t)z * MROWS * HC;
        W = W0 + (size_t)z * TC * HC;
        Cf += (size_t)z * MROWS * TC;
    } else if (MODE == 8) {
        A += (size_t)z * MROWS * TC;
        W = W0 + (size_t)z * HC * TC;
        Ch += (size_t)z * MROWS * HC;
    } else {
        W = ((rm0 & 1023) < T0C) ? Wa : Wb;
    }

    const uint32_t a_off =
        (uint32_t)(((warp_m * 64 + (lane & 15)) * SROWH + (lane >> 4) * 8) * 2);
    const uint32_t b_off =
        (uint32_t)((128 * SROWH +
                    (warp_n * 64 + (lane & 7) + ((lane >> 4) & 1) * 8) * SROWH +
                    ((lane >> 3) & 1) * 8) * 2);

    float acc[4][8][4];
    #pragma unroll
    for (int t = 0; t < 4; t++)
        #pragma unroll
        for (int j = 0; j < 8; j++)
            #pragma unroll
            for (int e = 0; e < 4; e++) acc[t][j][e] = 0.f;

    auto issue = [&](int c) {
        int stg = c - (c / NSTAGE) * NSTAGE;
        uint32_t sb = sbase + stg * (STGH * 2);
        int kb = c << 6;
        #pragma unroll
        for (int it = 0; it < 16; it++) {
            int idx = it * 128 + tid;
            int row = (idx >> 3) & 127;
            int sg = (idx & 7) << 3;
            if (idx < 1024)
                cp16(sb + (uint32_t)(row * SROWH + sg) * 2,
                     A + (size_t)(rm0 + row) * Kdim + kb + sg);
            else
                cp16(sb + (uint32_t)(128 * SROWH + row * SROWH + sg) * 2,
                     W + (size_t)(wr0 + row) * Kdim + kb + sg);
        }
    };

    auto compute = [&](int stg) {
        uint32_t sb = sbase + stg * (STGH * 2);
        #pragma unroll
        for (int ks = 0; ks < 4; ks++) {
            uint32_t af[4][4], bf[8][2];
            #pragma unroll
            for (int t = 0; t < 4; t++)
                ldsm4(af[t], sb + a_off + (uint32_t)((t * 16 * SROWH + ks * 16) * 2));
            #pragma unroll
            for (int p = 0; p < 4; p++)
                ldsm4(&bf[2 * p][0], sb + b_off + (uint32_t)((p * 16 * SROWH + ks * 16) * 2));
            #pragma unroll
            for (int t = 0; t < 4; t++)
                #pragma unroll
                for (int j = 0; j < 8; j++)
                    mma16(acc[t][j], af[t], bf[j]);
        }
    };

    int nch;
    if (MODE == 8) {
        int kmax = max(T0C, (rm0 >> 3) + 16);
        nch = (kmax + 63) >> 6;
    } else {
        nch = Kdim >> 6;
    }

    issue(0); CP_COMMIT();
    issue(1); CP_COMMIT();
    int stg = 0;
    for (int c = 0; c < nch; c++) {
        CP_WAIT(1);
        __syncthreads();
        compute(stg);
        if (++stg == NSTAGE) stg = 0;
        int nx = c + NSTAGE - 1;
        if (nx < nch) issue(nx);
        CP_COMMIT();
    }

    // ---------------- epilogue ----------------
    bool vtile = (MODE == 6) && (blockIdx.y >= 18);
    #pragma unroll
    for (int t = 0; t < 4; t++) {
        #pragma unroll
        for (int j = 0; j < 8; j++) {
            int c = rn0 + warp_n * 64 + j * 8 + (lane & 3) * 2;
            #pragma unroll
            for (int h = 0; h < 2; h++) {
                int r = rm0 + warp_m * 64 + t * 16 + (lane >> 2) + h * 8;
                float v0 = acc[t][j][h * 2 + 0];
                float v1 = acc[t][j][h * 2 + 1];
                if (MODE == 6) {
                    if (vtile) {
                        // direct transposed fp16 V write: vT[b][vd][t]
                        int b = r >> 10, tt = r & 1023;
                        int vd = c - (NHD + HC);
                        size_t base = ((size_t)b * HC + vd) * TC + tt;
                        Vt[base]      = __float2half(v0);
                        Vt[base + TC] = __float2half(v1);
                    } else {
                        float2 v = {v0, v1};
                        *(float2*)&Cf[(size_t)r * Nout + c] = v;
                    }
                } else if (MODE == 8) {
                    *(__half2*)&Ch[(size_t)r * Nout + c] = __floats2half2_rn(v0, v1);
                } else if (MODE == 1) {
                    int b = r >> 10, tt = r & 1023;
                    const float* xp = (tt < T0C)
                        ? X0 + ((size_t)b * T0C + tt) * DC + c
                        : X1 + ((size_t)b * T1C + (tt - T0C)) * DC + c;
                    float2 xv = *(const float2*)xp;
                    float2 v = {v0 + xv.x, v1 + xv.y};
                    *(float2*)&Cf[(size_t)r * DC + c] = v;
                } else if (MODE == 2) {
                    float2 rv = *(const float2*)&Radd[(size_t)r * DC + c];
                    int b = r >> 10, tt = r & 1023;
                    size_t dst = (tt < T0C)
                        ? ((size_t)b * T0C + tt) * DC + c
                        : (size_t)BB * T0C * DC + ((size_t)b * T1C + (tt - T0C)) * DC + c;
                    float2 v = {v0 + rv.x, v1 + rv.y};
                    *(float2*)&Cf[dst] = v;
                } else if (MODE == 7) {
                    float2 v = {v0, v1};
                    *(float2*)&Cf[(size_t)r * TC + c] = v;
                }
            }
        }
    }
}

// ================= fused gate+up FFN kernel (ldmatrix, 1 barrier/chunk) =================
#define STGG (384 * SROWH)

__global__ void __launch_bounds__(256, 1)
ffn_gateup(const __half* __restrict__ A,
           const __half* __restrict__ G0, const __half* __restrict__ G1,
           const __half* __restrict__ U0, const __half* __restrict__ U1,
           __half* __restrict__ Cg) {
    extern __shared__ __half smh[];
    uint32_t sbase = smem_u32(smh);
    int tid = threadIdx.x, wid = tid >> 5, lane = tid & 31;
    int w4 = wid & 3;
    int is_up = wid >> 2;
    int warp_m = w4 & 1, warp_n = w4 >> 1;
    int rm0 = blockIdx.x * 128;
    int rn0 = blockIdx.y * 128;
    bool seg1 = (rm0 & 1023) >= T0C;
    const __half* Wg = seg1 ? G1 : G0;
    const __half* Wu = seg1 ? U1 : U0;

    const uint32_t a_off =
        (uint32_t)(((warp_m * 64 + (lane & 15)) * SROWH + (lane >> 4) * 8) * 2);
    const uint32_t b_off =
        (uint32_t)(((128 + is_up * 128) * SROWH +
                    (warp_n * 64 + (lane & 7) + ((lane >> 4) & 1) * 8) * SROWH +
                    ((lane >> 3) & 1) * 8) * 2);

    float acc[4][8][4];
    #pragma unroll
    for (int t = 0; t < 4; t++)
        #pragma unroll
        for (int j = 0; j < 8; j++)
            #pragma unroll
            for (int e = 0; e < 4; e++) acc[t][j][e] = 0.f;

    auto issue = [&](int c) {
        int stg = c - (c / NSTAGE) * NSTAGE;
        uint32_t sb = sbase + stg * (STGG * 2);
        int kb = c << 6;
        #pragma unroll
        for (int it = 0; it < 12; it++) {
            int idx = it * 256 + tid;
            int row = idx >> 3;
            int sg = (idx & 7) << 3;
            const __half* src;
            if (row < 128)
                src = A + (size_t)(rm0 + row) * DC + kb + sg;
            else if (row < 256)
                src = Wg + (size_t)(rn0 + row - 128) * DC + kb + sg;
            else
                src = Wu + (size_t)(rn0 + row - 256) * DC + kb + sg;
            cp16(sb + (uint32_t)(row * SROWH + sg) * 2, src);
        }
    };

    auto compute = [&](int stg) {
        uint32_t sb = sbase + stg * (STGG * 2);
        #pragma unroll
        for (int ks = 0; ks < 4; ks++) {
            uint32_t af[4][4], bf[8][2];
            #pragma unroll
            for (int t = 0; t < 4; t++)
                ldsm4(af[t], sb + a_off + (uint32_t)((t * 16 * SROWH + ks * 16) * 2));
            #pragma unroll
            for (int p = 0; p < 4; p++)
                ldsm4(&bf[2 * p][0], sb + b_off + (uint32_t)((p * 16 * SROWH + ks * 16) * 2));
            #pragma unroll
            for (int t = 0; t < 4; t++)
                #pragma unroll
                for (int j = 0; j < 8; j++)
                    mma16(acc[t][j], af[t], bf[j]);
        }
    };

    const int nch = DC >> 6;
    issue(0); CP_COMMIT();
    issue(1); CP_COMMIT();
    int stg = 0;
    for (int c = 0; c < nch; c++) {
        CP_WAIT(1);
        __syncthreads();
        compute(stg);
        if (++stg == NSTAGE) stg = 0;
        int nx = c + NSTAGE - 1;
        if (nx < nch) issue(nx);
        CP_COMMIT();
    }

    CP_WAIT(0);
    __syncthreads();

    float* gt = (float*)smh;
    if (!is_up) {
        #pragma unroll
        for (int t = 0; t < 4; t++)
            #pragma unroll
            for (int j = 0; j < 8; j++) {
                int cl = warp_n * 64 + j * 8 + (lane & 3) * 2;
                #pragma unroll
                for (int h = 0; h < 2; h++) {
                    int rl = warp_m * 64 + t * 16 + (lane >> 2) + h * 8;
                    gt[rl * 132 + cl]     = gelu_tanh(acc[t][j][h * 2 + 0]);
                    gt[rl * 132 + cl + 1] = gelu_tanh(acc[t][j][h * 2 + 1]);
                }
            }
    }
    __syncthreads();
    if (is_up) {
        #pragma unroll
        for (int t = 0; t < 4; t++)
            #pragma unroll
            for (int j = 0; j < 8; j++) {
                int cl = warp_n * 64 + j * 8 + (lane & 3) * 2;
                int c = rn0 + cl;
                #pragma unroll
                for (int h = 0; h < 2; h++) {
                    int rl = warp_m * 64 + t * 16 + (lane >> 2) + h * 8;
                    int r = rm0 + rl;
                    float g0 = gt[rl * 132 + cl];
                    float g1 = gt[rl * 132 + cl + 1];
                    *(__half2*)&Cg[(size_t)r * FC + c] =
                        __floats2half2_rn(g0 * acc[t][j][h * 2 + 0],
                                          g1 * acc[t][j][h * 2 + 1]);
                }
            }
    }
}

// ================= split weight conversion =================
template <int NR>
struct CvtArgsN {
    const float4* s[NR];
    uint2* d[NR];
    size_t sz[NR];
};

template <int NR>
__global__ void cvt_n(CvtArgsN<NR> a) {
    size_t i = (size_t)blockIdx.x * 256 + threadIdx.x;
    size_t base = 0;
    #pragma unroll
    for (int r = 0; r < NR; r++) {
        if (i < base + a.sz[r]) {
            size_t k = i - base;
            float4 v = a.s[r][k];
            __half2 h0 = __floats2half2_rn(v.x, v.y);
            __half2 h1 = __floats2half2_rn(v.z, v.w);
            uint2 u = {h2u(h0), h2u(h1)};
            a.d[r][k] = u;
            return;
        }
        base += a.sz[r];
    }
}

#define Q4 ((size_t)NHD * DC / 4)
#define KV4 ((size_t)HC * DC / 4)
#define G4 ((size_t)FC * DC / 4)

// ================= elementwise =================
__device__ __forceinline__ float warp_sum(float v) {
    #pragma unroll
    for (int o = 16; o; o >>= 1) v += __shfl_down_sync(0xffffffffu, v, o);
    return v;
}

__global__ void rms_seg_kernel(const float* __restrict__ x0, const float* __restrict__ x1,
                               const float* __restrict__ s0, const float* __restrict__ s1,
                               __half* __restrict__ out) {
    int row = blockIdx.x;
    int b = row >> 10, t = row & 1023;
    const float* x; const float* s;
    if (t < T0C) { x = x0 + ((size_t)b*T0C + t)*DC; s = s0; }
    else         { x = x1 + ((size_t)b*T1C + (t - T0C))*DC; s = s1; }
    float ss = 0.f;
    for (int d = threadIdx.x; d < DC; d += 256) { float v = x[d]; ss += v*v; }
    __shared__ float red[8];
    ss = warp_sum(ss);
    if ((threadIdx.x & 31) == 0) red[threadIdx.x >> 5] = ss;
    __syncthreads();
    if (threadIdx.x < 8) {
        float v = red[threadIdx.x];
        #pragma unroll
        for (int o = 4; o; o >>= 1) v += __shfl_down_sync(0xffu, v, o);
        if (threadIdx.x == 0) red[0] = v;
    }
    __syncthreads();
    float inv = rsqrtf(red[0] * (1.f / DC) + 1e-6f);
    __half* o = out + (size_t)row * DC;
    for (int d = threadIdx.x; d < DC; d += 256)
        o[d] = __float2half(x[d] * inv * (1.f + s[d]));
}

__global__ void rms_cont_kernel(const float* __restrict__ xin,
                                const float* __restrict__ s0, const float* __restrict__ s1,
                                __half* __restrict__ out) {
    int row = blockIdx.x;
    int t = row & 1023;
    const float* x = xin + (size_t)row * DC;
    const float* s = (t < T0C) ? s0 : s1;
    float ss = 0.f;
    for (int d = threadIdx.x; d < DC; d += 256) { float v = x[d]; ss += v*v; }
    __shared__ float red[8];
    ss = warp_sum(ss);
    if ((threadIdx.x & 31) == 0) red[threadIdx.x >> 5] = ss;
    __syncthreads();
    if (threadIdx.x < 8) {
        float v = red[threadIdx.x];
        #pragma unroll
        for (int o = 4; o; o >>= 1) v += __shfl_down_sync(0xffu, v, o);
        if (threadIdx.x == 0) red[0] = v;
    }
    __syncthreads();
    float inv = rsqrtf(red[0] * (1.f / DC) + 1e-6f);
    __half* o = out + (size_t)row * DC;
    for (int d = threadIdx.x; d < DC; d += 256)
        o[d] = __float2half(x[d] * inv * (1.f + s[d]));
}

#define L2_10K 13.287712379549449f   // log2(10000)

__global__ void rope_q_kernel(const float* __restrict__ qkv, __half* __restrict__ qout) {
    int head = blockIdx.x;
    int bt = head >> 3, n = head & 7;
    int t = bt & 1023;
    int i = threadIdx.x;
    float rad = (float)t * exp2f((float)i * (-L2_10K / 128.f));
    float s, c;
    sincosf(rad, &s, &c);
    size_t base = (size_t)bt * QKVW + (size_t)n * HC;
    float x1 = qkv[base + i], x2 = qkv[base + 128 + i];
    const float sc = 0.0625f;
    size_t ob = (size_t)head * HC;
    qout[ob + i]       = __float2half((x1 * c - x2 * s) * sc);
    qout[ob + 128 + i] = __float2half((x2 * c + x1 * s) * sc);
}

__global__ void rope_k_kernel(const float* __restrict__ qkv, __half* __restrict__ kd) {
    int bt = blockIdx.x;
    int t = bt & 1023;
    int i = threadIdx.x;
    float rad = (float)t * exp2f((float)i * (-L2_10K / 128.f));
    float s, c;
    sincosf(rad, &s, &c);
    size_t base = (size_t)bt * QKVW + NHD;
    float x1 = qkv[base + i], x2 = qkv[base + 128 + i];
    size_t ob = (size_t)bt * HC;
    kd[ob + i]       = __float2half(x1 * c - x2 * s);
    kd[ob + 128 + i] = __float2half(x2 * c + x1 * s);
}

// row softmax with valid-span bounds (masked S never read; P tail zeros
// only up to what the AV tile reads).
__global__ void softmax_kernel(const float* __restrict__ S, __half* __restrict__ P) {
    int row = blockIdx.x;
    int tt = (row & (MROWS - 1)) >> 3;
    int Lv = max(T0C, tt + 1);
    int Lw = (max(T0C, (tt & ~15) + 16) + 63) & ~63;
    const float* srow = S + (size_t)row * TC;
    __half* prow = P + (size_t)row * TC;
    int tid = threadIdx.x;
    float4 v[2];
    #pragma unroll
    for (int q = 0; q < 2; q++) {
        int j = q * 512 + tid * 4;
        if (j < Lw) {
            if (j + 4 <= Lv) {
                v[q] = *(const float4*)&srow[j];
            } else {
                float t4[4];
                #pragma unroll
                for (int k = 0; k < 4; k++)
                    t4[k] = (j + k < Lv) ? srow[j + k] : -3.4e38f;
                v[q] = make_float4(t4[0], t4[1], t4[2], t4[3]);
            }
        } else {
            v[q] = make_float4(-3.4e38f, -3.4e38f, -3.4e38f, -3.4e38f);
        }
    }
    float m = fmaxf(fmaxf(v[0].x, v[0].y), fmaxf(v[0].z, v[0].w));
    m = fmaxf(m, fmaxf(fmaxf(v[1].x, v[1].y), fmaxf(v[1].z, v[1].w)));
    __shared__ float red[4];
    #pragma unroll
    for (int o = 16; o; o >>= 1) m = fmaxf(m, __shfl_xor_sync(0xffffffffu, m, o));
    if ((tid & 31) == 0) red[tid >> 5] = m;
    __syncthreads();
    m = fmaxf(fmaxf(red[0], red[1]), fmaxf(red[2], red[3]));
    float l = 0.f;
    #pragma unroll
    for (int q = 0; q < 2; q++) {
        float* e = &v[q].x;
        #pragma unroll
        for (int i = 0; i < 4; i++) {
            float p = __expf(fmaxf(e[i] - m, -80.f));
            e[i] = p;
            l += p;
        }
    }
    #pragma unroll
    for (int o = 16; o; o >>= 1) l += __shfl_xor_sync(0xffffffffu, l, o);
    if ((tid & 31) == 0) red[tid >> 5] = l;
    __syncthreads();
    l = red[0] + red[1] + red[2] + red[3];
    float inv = 1.f / l;
    #pragma unroll
    for (int q = 0; q < 2; q++) {
        int j = q * 512 + tid * 4;
        if (j < Lw) {
            __half2 h0 = __floats2half2_rn(v[q].x * inv, v[q].y * inv);
            __half2 h1 = __floats2half2_rn(v[q].z * inv, v[q].w * inv);
            uint2 u = {h2u(h0), h2u(h1)};
            *(uint2*)&prow[j] = u;
        }
    }
}

// ================= launch =================
extern "C" void kernel_launch(void* const* d_in, const int* in_sizes, int n_in,
                              void* d_out, int out_size) {
    const float* x0  = (const float*)d_in[0];
    const float* x1  = (const float*)d_in[1];
    const float* qw0 = (const float*)d_in[4];
    const float* kw0 = (const float*)d_in[5];
    const float* vw0 = (const float*)d_in[6];
    const float* ow0 = (const float*)d_in[7];
    const float* gw0 = (const float*)d_in[8];
    const float* uw0 = (const float*)d_in[9];
    const float* dw0 = (const float*)d_in[10];
    const float* pa0 = (const float*)d_in[11];
    const float* pf0 = (const float*)d_in[12];
    const float* qw1 = (const float*)d_in[13];
    const float* kw1 = (const float*)d_in[14];
    const float* vw1 = (const float*)d_in[15];
    const float* ow1 = (const float*)d_in[16];
    const float* gw1 = (const float*)d_in[17];
    const float* uw1 = (const float*)d_in[18];
    const float* dw1 = (const float*)d_in[19];
    const float* pa1 = (const float*)d_in[20];
    const float* pf1 = (const float*)d_in[21];

    __half *qwh, *kwh, *vwh, *owh, *gwh, *uwh, *dwh;
    __half *preh, *qhh, *kdhh, *vTh, *Ph, *ench, *hidh, *guh;
    float *qkvf, *S, *resid;
    cudaGetSymbolAddress((void**)&qwh, g_qwh);
    cudaGetSymbolAddress((void**)&kwh, g_kwh);
    cudaGetSymbolAddress((void**)&vwh, g_vwh);
    cudaGetSymbolAddress((void**)&owh, g_owh);
    cudaGetSymbolAddress((void**)&gwh, g_gwh);
    cudaGetSymbolAddress((void**)&uwh, g_uwh);
    cudaGetSymbolAddress((void**)&dwh, g_dwh);
    cudaGetSymbolAddress((void**)&preh, g_preh);
    cudaGetSymbolAddress((void**)&qkvf, g_qkvf);
    cudaGetSymbolAddress((void**)&qhh,  g_qhh);
    cudaGetSymbolAddress((void**)&kdhh, g_kdhh);
    cudaGetSymbolAddress((void**)&vTh,  g_vTh);
    cudaGetSymbolAddress((void**)&S,    g_S);
    cudaGetSymbolAddress((void**)&Ph,   g_Ph);
    cudaGetSymbolAddress((void**)&ench, g_ench);
    cudaGetSymbolAddress((void**)&resid, g_resid);
    cudaGetSymbolAddress((void**)&hidh, g_hidh);
    cudaGetSymbolAddress((void**)&guh,  g_guh);

    const int SMEMH = NSTAGE * STGH * 2;    // 110592
    const int SMEMG = NSTAGE * STGG * 2;    // 165888
    cudaFuncSetAttribute(mma_gemm<1>, cudaFuncAttributeMaxDynamicSharedMemorySize, SMEMH);
    cudaFuncSetAttribute(mma_gemm<2>, cudaFuncAttributeMaxDynamicSharedMemorySize, SMEMH);
    cudaFuncSetAttribute(mma_gemm<6>, cudaFuncAttributeMaxDynamicSharedMemorySize, SMEMH);
    cudaFuncSetAttribute(mma_gemm<7>, cudaFuncAttributeMaxDynamicSharedMemorySize, SMEMH);
    cudaFuncSetAttribute(mma_gemm<8>, cudaFuncAttributeMaxDynamicSharedMemorySize, SMEMH);
    cudaFuncSetAttribute(ffn_gateup, cudaFuncAttributeMaxDynamicSharedMemorySize, SMEMG);

    static cudaStream_t s_aux = nullptr, s_aux2 = nullptr;
    static cudaEvent_t ev_fork = nullptr, ev_join = nullptr;
    static cudaEvent_t ev_qkv = nullptr, ev_ew = nullptr;
    if (s_aux == nullptr) {
        cudaStreamCreateWithFlags(&s_aux, cudaStreamNonBlocking);
        cudaStreamCreateWithFlags(&s_aux2, cudaStreamNonBlocking);
        cudaEventCreateWithFlags(&ev_fork, cudaEventDisableTiming);
        cudaEventCreateWithFlags(&ev_join, cudaEventDisableTiming);
        cudaEventCreateWithFlags(&ev_qkv, cudaEventDisableTiming);
        cudaEventCreateWithFlags(&ev_ew, cudaEventDisableTiming);
    }

    // ---- fork: big FFN weight cvt (gw/uw/dw) on aux stream ----
    cudaEventRecord(ev_fork, 0);
    cudaStreamWaitEvent(s_aux, ev_fork, 0);
    {
        CvtArgsN<6> a;
        const float* srcs[6] = {gw0, gw1, uw0, uw1, dw0, dw1};
        __half* dsts[6] = {gwh, gwh + (size_t)FC * DC,
                           uwh, uwh + (size_t)FC * DC,
                           dwh, dwh + (size_t)DC * FC};
        for (int r = 0; r < 6; r++) {
            a.s[r] = (const float4*)srcs[r];
            a.d[r] = (uint2*)dsts[r];
            a.sz[r] = G4;
        }
        size_t tot = 6 * G4;
        cvt_n<6><<<(unsigned)((tot + 255) / 256), 256, 0, s_aux>>>(a);
    }
    cudaEventRecord(ev_join, s_aux);

    // ---- main stream: small QKV/O weight cvt ----
    {
        CvtArgsN<8> a;
        const float* srcs[8] = {qw0, qw1, kw0, kw1, vw0, vw1, ow0, ow1};
        __half* dsts[8] = {qwh, qwh + (size_t)NHD * DC,
                           kwh, kwh + (size_t)HC * DC,
                           vwh, vwh + (size_t)HC * DC,
                           owh, owh + (size_t)DC * NHD};
        size_t szs[8] = {Q4, Q4, KV4, KV4, KV4, KV4, Q4, Q4};
        for (int r = 0; r < 8; r++) {
            a.s[r] = (const float4*)srcs[r];
            a.d[r] = (uint2*)dsts[r];
            a.sz[r] = szs[r];
        }
        size_t tot = 4 * Q4 + 4 * KV4;
        cvt_n<8><<<(unsigned)((tot + 255) / 256), 256>>>(a);
    }

    // 1. pre = RMSNorm(x) -> fp16
    rms_seg_kernel<<<BB * TC, 256>>>(x0, x1, pa0, pa1, preh);
    // 2. fused QKV -> fp32 qkv (q,k) + DIRECT fp16 transposed V
    mma_gemm<6><<<dim3(32, 20), 128, SMEMH>>>(preh,
        qwh, qwh + (size_t)NHD * DC, kwh, kwh + (size_t)HC * DC,
        vwh, vwh + (size_t)HC * DC,
        qkvf, QKVW, DC, nullptr, nullptr, nullptr, vTh);

    // ---- fork elementwise: rope_k on s_aux2, rope_q on main ----
    cudaEventRecord(ev_qkv, 0);
    cudaStreamWaitEvent(s_aux2, ev_qkv, 0);
    rope_k_kernel<<<BB * TC, 128, 0, s_aux2>>>(qkvf, kdhh);
    cudaEventRecord(ev_ew, s_aux2);
    rope_q_kernel<<<BB * TC * NQ, 128>>>(qkvf, qhh);
    cudaStreamWaitEvent(0, ev_ew, 0);

    // 4a. scores (fp16 MMA, fp32 out); fully-masked tiles skipped
    mma_gemm<7><<<dim3(MROWS / 128, TC / 128, BB), 128, SMEMH>>>(
        qhh, kdhh, nullptr, nullptr, nullptr, nullptr, nullptr,
        S, TC, HC, nullptr, nullptr, nullptr, nullptr);
    // 4b. bounded softmax -> fp16 probs
    softmax_kernel<<<BB * MROWS, 128>>>(S, Ph);
    // 4c. enc = P @ vT.T -> fp16 (K-loop truncated to valid span)
    mma_gemm<8><<<dim3(MROWS / 128, HC / 128, BB), 128, SMEMH>>>(
        Ph, vTh, nullptr, nullptr, nullptr, nullptr, nullptr,
        ench, HC, TC, nullptr, nullptr, nullptr, nullptr);
    // 5. O-proj + residual -> fp32 resid
    mma_gemm<1><<<dim3(32, 16), 128, SMEMH>>>(ench,
        owh, owh + (size_t)DC * NHD, nullptr, nullptr, nullptr, nullptr,
        resid, DC, NHD, x0, x1, nullptr, nullptr);
    // 6. hid = RMSNorm(resid) -> fp16
    rms_cont_kernel<<<BB * TC, 256>>>(resid, pf0, pf1, hidh);

    // ---- join: FFN weights must be converted before gate/up/down ----
    cudaStreamWaitEvent(0, ev_join, 0);

    // 7+8. fused gate+up: gu = gelu(hid@gw.T) * (hid@uw.T) -> fp16
    ffn_gateup<<<dim3(32, 128), 256, SMEMG>>>(hidh,
        gwh, gwh + (size_t)FC * DC, uwh, uwh + (size_t)FC * DC, guh);
    // 9. down-proj + residual -> segmented fp32 d_out
    mma_gemm<2><<<dim3(32, 16), 128, SMEMH>>>(guh,
        dwh, dwh + (size_t)DC * FC, nullptr, nullptr, nullptr, nullptr,
        d_out, DC, FC, nullptr, nullptr, resid, nullptr);
}